// round 6
// baseline (speedup 1.0000x reference)
#include <cuda_runtime.h>
#include <math.h>

typedef unsigned int   u32;
typedef unsigned short u16;
typedef unsigned long long ull;

// ---------------------------------------------------------------------------
// Scratch buffers (device globals — allocation-free per harness rules)
// ---------------------------------------------------------------------------
__device__ float g_a1[18585600];     // conv1 out [64,96,55,55]
__device__ float g_p1[4478976];      // pool1     [64,96,27,27]
__device__ float g_a2[11943936];     // conv2 out [64,256,27,27]
__device__ float g_p2[3211264];      // pool2     [64,256,14,14]
__device__ float g_a3[4816896];      // conv3 out [64,384,14,14]
__device__ float g_a4[4816896];      // conv4 out
__device__ float g_a5[3211264];      // conv5 out [64,256,14,14]
__device__ float g_p3[589824];       // pool3     [64,256,6,6]
__device__ float g_pc[589824];       // primarycaps conv out
__device__ float g_u[589824];        // squashed capsules [64,1152,8]
__device__ float g_xh[119144448];    // x_hat [64,101,1152,16]
__device__ float g_bl[7446528];      // b logits [64,101,1152]
__device__ float g_cc[7446528];      // coupling coeffs
__device__ float g_v[103424];        // v [64,101,16]
__device__ float g_f1[262144];       // fc1 out [64,4096]
__device__ float g_f2[262144];       // fc2 out [64,4096]
__device__ u32   g_packA[10000000];  // packed hi|lo activations (per layer)
__device__ u32   g_packW[1400000];   // split weight planes: hi u16[]; lo u16[]

// ---------------------------------------------------------------------------
// bf16 hi/lo split: x ≈ hi + lo (both bf16 RNE). packed u32 = (hi<<16)|lo
// ---------------------------------------------------------------------------
__device__ __forceinline__ u32 pack_hilo(float x)
{
    u32 u  = __float_as_uint(x);
    u32 hi = (u + 0x7fffu + ((u >> 16) & 1u)) >> 16;
    float hf = __uint_as_float(hi << 16);
    u32 v  = __float_as_uint(x - hf);
    u32 lo = (v + 0x7fffu + ((v >> 16) & 1u)) >> 16;
    return (hi << 16) | lo;
}

__global__ void pack_act_k(const float* __restrict__ src, u32* __restrict__ dst, int n)
{
    int i = blockIdx.x * blockDim.x + threadIdx.x;
    if (i < n) dst[i] = pack_hilo(src[i]);
}

__global__ void pack_wsplit_k(const float* __restrict__ src,
                              u16* __restrict__ hi, u16* __restrict__ lo,
                              int M, int K, int Kpad, int tot)
{
    int i = blockIdx.x * blockDim.x + threadIdx.x;
    if (i >= tot) return;
    int m = i / Kpad, k = i - m * Kpad;
    float x = (m < M && k < K) ? src[(long)m * K + k] : 0.f;
    u32 p = pack_hilo(x);
    hi[i] = (u16)(p >> 16);
    lo[i] = (u16)(p & 0xffffu);
}

// ---------------------------------------------------------------------------
// mma.sync bf16 + cp.async helpers
// ---------------------------------------------------------------------------
__device__ __forceinline__ void mma_bf16(float* d, const u32* a, u32 b0, u32 b1)
{
    asm("mma.sync.aligned.m16n8k16.row.col.f32.bf16.bf16.f32 "
        "{%0,%1,%2,%3}, {%4,%5,%6,%7}, {%8,%9}, {%0,%1,%2,%3};"
        : "+f"(d[0]), "+f"(d[1]), "+f"(d[2]), "+f"(d[3])
        : "r"(a[0]), "r"(a[1]), "r"(a[2]), "r"(a[3]), "r"(b0), "r"(b1));
}

__device__ __forceinline__ void cp_async16(u32 dst, const void* src)
{
    asm volatile("cp.async.ca.shared.global [%0], [%1], 16;"
                 :: "r"(dst), "l"(src) : "memory");
}
__device__ __forceinline__ void cp_commit()
{
    asm volatile("cp.async.commit_group;" ::: "memory");
}
template<int N> __device__ __forceinline__ void cp_wait()
{
    asm volatile("cp.async.wait_group %0;" :: "n"(N) : "memory");
}

// ---------------------------------------------------------------------------
// Implicit-GEMM conv on mma.sync bf16, 2-term split (3 passes).
// 128x128 tile, BK=32, 8 warps (4x2), double-buffered smem, 80B row stride
// (conflict-free; 80KB/CTA -> 2 CTAs/SM).
// ---------------------------------------------------------------------------
static constexpr int CV_ROWB  = 80;
static constexpr int CV_ARR   = 128 * CV_ROWB;           // 10240
static constexpr int CV_AH = 0, CV_AL = CV_ARR, CV_BH = 2 * CV_ARR, CV_BL = 3 * CV_ARR;
static constexpr int CV_STAGE = 4 * CV_ARR;              // 40960
static constexpr int CV_SMEM  = 2 * CV_STAGE;            // 81920

template<int KH, int KW, int SS, int PP>
__global__ __launch_bounds__(256, 2)
void convhmma_k(const u16* __restrict__ whi, const u16* __restrict__ wlo,
                const u32* __restrict__ pin, const float* __restrict__ bias,
                float* __restrict__ outp,
                int M, int C, int H, int W, int OH, int OW,
                int K, int Kpad, int relu)
{
    extern __shared__ char smem[];
    const u32 sbase = (u32)__cvta_generic_to_shared(smem);

    const int tid  = threadIdx.x;
    const int wid  = tid >> 5, lane = tid & 31;
    const int g    = lane >> 2, qi = lane & 3;
    const int mwarp = (wid >> 1) * 32, nwarp = (wid & 1) * 64;
    const int KHW  = KH * KW;
    const int OHW  = OH * OW;
    const int N    = 64 * OHW;
    const int m0   = blockIdx.y * 128, n0 = blockIdx.x * 128;

    const int lrow = tid & 127;
    const int half = tid >> 7;

    const int gn = n0 + lrow;
    const bool nvalid = gn < N;
    const int bn = nvalid ? gn : 0;
    const int ow = bn % OW;
    const int t1 = bn / OW;
    const int oh = t1 % OH;
    const int bb = t1 / OH;
    const int ihb = oh * SS - PP, iwb = ow * SS - PP;
    const u32* inb = pin + (long)bb * C * H * W;

    const int nstage = Kpad / 32;

    auto issueA = [&](int ck, int buf) {
        const u16* srch = whi + (long)(m0 + lrow) * Kpad + ck * 32 + half * 16;
        const u16* srcl = wlo + (long)(m0 + lrow) * Kpad + ck * 32 + half * 16;
        u32 d = sbase + buf * CV_STAGE + lrow * CV_ROWB + half * 32;
        cp_async16(d + CV_AH,      srch);
        cp_async16(d + CV_AH + 16, srch + 8);
        cp_async16(d + CV_AL,      srcl);
        cp_async16(d + CV_AL + 16, srcl + 8);
        cp_commit();
    };

    u32 breg[16];
    auto loadB = [&](int ck) {
        int gk0 = ck * 32 + half * 16;
        int cc = gk0 / KHW;
        int r  = gk0 - cc * KHW;
        int kh = r / KW;
        int kw = r - kh * KW;
#pragma unroll
        for (int t = 0; t < 16; t++) {
            u32 v = 0u;
            if (nvalid && gk0 + t < K) {
                int ih = ihb + kh, iw = iwb + kw;
                if ((unsigned)ih < (unsigned)H && (unsigned)iw < (unsigned)W)
                    v = inb[((long)cc * H + ih) * W + iw];
            }
            breg[t] = v;
            if (++kw == KW) { kw = 0; if (++kh == KH) { kh = 0; ++cc; } }
        }
    };
    auto storeB = [&](int buf) {
        u32 h[8], l[8];
#pragma unroll
        for (int t = 0; t < 8; t++) {
            h[t] = __byte_perm(breg[2 * t], breg[2 * t + 1], 0x7632);
            l[t] = __byte_perm(breg[2 * t], breg[2 * t + 1], 0x5410);
        }
        char* d = smem + buf * CV_STAGE + lrow * CV_ROWB + half * 32;
        *(uint4*)(d + CV_BH)      = make_uint4(h[0], h[1], h[2], h[3]);
        *(uint4*)(d + CV_BH + 16) = make_uint4(h[4], h[5], h[6], h[7]);
        *(uint4*)(d + CV_BL)      = make_uint4(l[0], l[1], l[2], l[3]);
        *(uint4*)(d + CV_BL + 16) = make_uint4(l[4], l[5], l[6], l[7]);
    };

    float acc[2][8][4];
#pragma unroll
    for (int i = 0; i < 2; i++)
#pragma unroll
        for (int j = 0; j < 8; j++)
#pragma unroll
            for (int q = 0; q < 4; q++) acc[i][j][q] = 0.f;

    int buf = 0;
    issueA(0, 0);
    loadB(0);

    for (int ck = 0; ck < nstage; ck++) {
        storeB(buf);
        cp_wait<0>();
        __syncthreads();
        if (ck + 1 < nstage) {
            issueA(ck + 1, buf ^ 1);
            loadB(ck + 1);
        }

        const char* st = smem + buf * CV_STAGE;
#pragma unroll
        for (int kk = 0; kk < 2; kk++) {
            u32 ah[2][4], al[2][4];
#pragma unroll
            for (int mt = 0; mt < 2; mt++) {
                const char* rA = st + (mwarp + mt * 16 + g) * CV_ROWB + kk * 32 + qi * 4;
                ah[mt][0] = *(const u32*)(rA + CV_AH);
                ah[mt][1] = *(const u32*)(rA + CV_AH + 8 * CV_ROWB);
                ah[mt][2] = *(const u32*)(rA + CV_AH + 16);
                ah[mt][3] = *(const u32*)(rA + CV_AH + 8 * CV_ROWB + 16);
                al[mt][0] = *(const u32*)(rA + CV_AL);
                al[mt][1] = *(const u32*)(rA + CV_AL + 8 * CV_ROWB);
                al[mt][2] = *(const u32*)(rA + CV_AL + 16);
                al[mt][3] = *(const u32*)(rA + CV_AL + 8 * CV_ROWB + 16);
            }
#pragma unroll
            for (int nt = 0; nt < 8; nt++) {
                const char* rB = st + (nwarp + nt * 8 + g) * CV_ROWB + kk * 32 + qi * 4;
                u32 bh0 = *(const u32*)(rB + CV_BH);
                u32 bh1 = *(const u32*)(rB + CV_BH + 16);
                u32 bl0 = *(const u32*)(rB + CV_BL);
                u32 bl1 = *(const u32*)(rB + CV_BL + 16);
                mma_bf16(acc[0][nt], ah[0], bh0, bh1);
                mma_bf16(acc[1][nt], ah[1], bh0, bh1);
                mma_bf16(acc[0][nt], al[0], bh0, bh1);
                mma_bf16(acc[1][nt], al[1], bh0, bh1);
                mma_bf16(acc[0][nt], ah[0], bl0, bl1);
                mma_bf16(acc[1][nt], ah[1], bl0, bl1);
            }
        }
        __syncthreads();
        buf ^= 1;
    }

    // ---- epilogue: bias (+relu) + NCHW scatter
    int colb[16], colp[16];
    bool colok[16];
#pragma unroll
    for (int nt = 0; nt < 8; nt++)
#pragma unroll
        for (int q = 0; q < 2; q++) {
            int ci = nt * 2 + q;
            int n = n0 + nwarp + nt * 8 + 2 * qi + q;
            colok[ci] = n < N;
            int nc = colok[ci] ? n : 0;
            colb[ci] = nc / OHW;
            colp[ci] = nc - colb[ci] * OHW;
        }
#pragma unroll
    for (int mt = 0; mt < 2; mt++) {
        int mA = m0 + mwarp + mt * 16 + g;
        int mB = mA + 8;
        float bvA = (mA < M) ? bias[mA] : 0.f;
        float bvB = (mB < M) ? bias[mB] : 0.f;
#pragma unroll
        for (int nt = 0; nt < 8; nt++)
#pragma unroll
            for (int q = 0; q < 2; q++) {
                int ci = nt * 2 + q;
                if (!colok[ci]) continue;
                long base = ((long)colb[ci] * M) * OHW + colp[ci];
                if (mA < M) {
                    float v = acc[mt][nt][q] + bvA;
                    if (relu && v < 0.f) v = 0.f;
                    outp[base + (long)mA * OHW] = v;
                }
                if (mB < M) {
                    float v = acc[mt][nt][2 + q] + bvB;
                    if (relu && v < 0.f) v = 0.f;
                    outp[base + (long)mB * OHW] = v;
                }
            }
    }
}

// ---------------------------------------------------------------------------
// 64x64-tile f32x2 GEMM (FC layers).  B given [N,K]; C[n*M+m]
// ---------------------------------------------------------------------------
__global__ __launch_bounds__(256, 2) void gemm64_k(
    const float* __restrict__ A, const float* __restrict__ Bm,
    const float* __restrict__ bias, float* __restrict__ Cout,
    int M, int N, int K, int relu)
{
    __shared__ __align__(16) float As[16][64];
    __shared__ __align__(16) float Bs[16][64];

    const int tid = threadIdx.x;
    const int m0 = blockIdx.y * 64, n0 = blockIdx.x * 64;
    const int tx = tid & 15, ty = tid >> 4;
    const int lm = tid & 63;
    const int lk4 = (tid >> 6) * 4;

    ull acc[4][2];
#pragma unroll
    for (int i = 0; i < 4; i++) { acc[i][0] = 0ULL; acc[i][1] = 0ULL; }

    for (int k0 = 0; k0 < K; k0 += 16) {
        {
            int gm = m0 + lm;
            if (gm < M) {
                float4 av = *(const float4*)&A[(long)gm * K + k0 + lk4];
                As[lk4 + 0][lm] = av.x; As[lk4 + 1][lm] = av.y;
                As[lk4 + 2][lm] = av.z; As[lk4 + 3][lm] = av.w;
            } else {
                As[lk4 + 0][lm] = 0.f; As[lk4 + 1][lm] = 0.f;
                As[lk4 + 2][lm] = 0.f; As[lk4 + 3][lm] = 0.f;
            }
        }
        {
            int gn = n0 + lm;
            if (gn < N) {
                float4 bv = *(const float4*)&Bm[(long)gn * K + k0 + lk4];
                Bs[lk4 + 0][lm] = bv.x; Bs[lk4 + 1][lm] = bv.y;
                Bs[lk4 + 2][lm] = bv.z; Bs[lk4 + 3][lm] = bv.w;
            } else {
                Bs[lk4 + 0][lm] = 0.f; Bs[lk4 + 1][lm] = 0.f;
                Bs[lk4 + 2][lm] = 0.f; Bs[lk4 + 3][lm] = 0.f;
            }
        }
        __syncthreads();
#pragma unroll
        for (int kk = 0; kk < 16; kk++) {
            float4 a4 = *(const float4*)&As[kk][ty * 4];
            ulonglong2 bv = *(const ulonglong2*)&Bs[kk][tx * 4];
            ull bp[2] = {bv.x, bv.y};
            float av[4] = {a4.x, a4.y, a4.z, a4.w};
#pragma unroll
            for (int i = 0; i < 4; i++) {
                ull sa;
                asm("mov.b64 %0, {%1, %1};" : "=l"(sa) : "f"(av[i]));
#pragma unroll
                for (int j = 0; j < 2; j++)
                    asm("fma.rn.f32x2 %0, %1, %2, %0;"
                        : "+l"(acc[i][j]) : "l"(sa), "l"(bp[j]));
            }
        }
        __syncthreads();
    }

#pragma unroll
    for (int i = 0; i < 4; i++) {
        int m = m0 + ty * 4 + i;
        if (m >= M) continue;
        float bv = bias ? bias[m] : 0.f;
#pragma unroll
        for (int j = 0; j < 2; j++) {
            float lo, hi;
            asm("mov.b64 {%0, %1}, %2;" : "=f"(lo), "=f"(hi) : "l"(acc[i][j]));
            float v0 = lo + bv, v1 = hi + bv;
            if (relu) { if (v0 < 0.f) v0 = 0.f; if (v1 < 0.f) v1 = 0.f; }
            int nA = n0 + tx * 4 + 2 * j, nB = nA + 1;
            if (nA < N) Cout[(long)nA * M + m] = v0;
            if (nB < N) Cout[(long)nB * M + m] = v1;
        }
    }
}

// ---------------------------------------------------------------------------
// MaxPool (floor mode)
// ---------------------------------------------------------------------------
__global__ void maxpool_k(const float* __restrict__ in, float* __restrict__ out,
                          int C, int H, int W, int OH, int OW,
                          int ks, int stride, int pad, int total)
{
    int idx = blockIdx.x * blockDim.x + threadIdx.x;
    if (idx >= total) return;
    int ow = idx % OW;
    int t = idx / OW;
    int oh = t % OH; t /= OH;
    int c = t % C;
    int b = t / C;
    const float* p = in + (long)(b * C + c) * H * W;
    float mx = -3.4e38f;
    int h0 = oh * stride - pad, w0 = ow * stride - pad;
    for (int kh = 0; kh < ks; kh++) {
        int ih = h0 + kh;
        if (ih < 0 || ih >= H) continue;
        for (int kw = 0; kw < ks; kw++) {
            int iw = w0 + kw;
            if (iw < 0 || iw >= W) continue;
            float v = p[ih * W + iw];
            if (v > mx) mx = v;
        }
    }
    out[idx] = mx;
}

// ---------------------------------------------------------------------------
// squash8 (primary caps)
// ---------------------------------------------------------------------------
__global__ void squash8_k(const float* __restrict__ p, float* __restrict__ u, int ncaps)
{
    int idx = blockIdx.x * blockDim.x + threadIdx.x;
    if (idx >= ncaps) return;
    const float4* ip = (const float4*)(p + (long)idx * 8);
    float4 a = ip[0], b = ip[1];
    float sq = a.x*a.x + a.y*a.y + a.z*a.z + a.w*a.w
             + b.x*b.x + b.y*b.y + b.z*b.z + b.w*b.w;
    float sc = (sq / (1.f + sq)) / sqrtf(sq + 1e-8f);
    float4* op = (float4*)(u + (long)idx * 8);
    op[0] = make_float4(a.x*sc, a.y*sc, a.z*sc, a.w*sc);
    op[1] = make_float4(b.x*sc, b.y*sc, b.z*sc, b.w*sc);
}

// ---------------------------------------------------------------------------
// xhat v2: coalesced.  grid (9, 101), 128 threads.
//   smem: W[j, i-chunk] as 128 rows x 132 floats (16B-aligned, conflict-free)
//   thread t = i_local; per b: 16 outs contiguous -> warp writes 2KB runs.
// ---------------------------------------------------------------------------
static constexpr int XH_SMEM = 128 * 132 * 4;   // 67584

__global__ __launch_bounds__(128) void xhat2_k(
    const float* __restrict__ Wc, const float* __restrict__ u,
    float* __restrict__ xh)
{
    extern __shared__ float Ws[];
    const int j = blockIdx.y, i0 = blockIdx.x * 128, t = threadIdx.x;

    const float* wsrc = Wc + ((long)j * 1152 + i0) * 128;
    for (int idx = t; idx < 128 * 128; idx += 128) {
        int row = idx >> 7, col = idx & 127;
        Ws[row * 132 + col] = wsrc[idx];
    }
    __syncthreads();

    const float* wrow = Ws + t * 132;
    for (int b = 0; b < 64; b++) {
        const float4* up = (const float4*)(u + ((long)b * 1152 + i0 + t) * 8);
        float4 u0 = up[0], u1 = up[1];
        float* op = xh + (((long)b * 101 + j) * 1152 + i0 + t) * 16;
#pragma unroll
        for (int og = 0; og < 4; og++) {
            float o[4];
#pragma unroll
            for (int q = 0; q < 4; q++) {
                const float4* w4 = (const float4*)(wrow + (og * 4 + q) * 8);
                float4 w0 = w4[0], w1 = w4[1];
                o[q] = w0.x*u0.x + w0.y*u0.y + w0.z*u0.z + w0.w*u0.w
                     + w1.x*u1.x + w1.y*u1.y + w1.z*u1.z + w1.w*u1.w;
            }
            ((float4*)op)[og] = make_float4(o[0], o[1], o[2], o[3]);
        }
    }
}

// ---------------------------------------------------------------------------
// routing: reduce + fused squash -> v directly
// ---------------------------------------------------------------------------
__global__ void route_reduce_k(const float* __restrict__ xh,
                               const float* __restrict__ c,
                               float* __restrict__ vout)
{
    int bj = blockIdx.x;
    int tid = threadIdx.x;
    const float* xb = xh + (long)bj * 1152 * 16;
    float acc[16];
#pragma unroll
    for (int o = 0; o < 16; o++) acc[o] = 0.f;
    for (int i = tid; i < 1152; i += 128) {
        float cw = c ? c[(long)bj * 1152 + i] : (1.f / 101.f);
        const float4* xp = (const float4*)(xb + (long)i * 16);
        float4 x0 = xp[0], x1 = xp[1], x2 = xp[2], x3 = xp[3];
        acc[0]  += cw * x0.x; acc[1]  += cw * x0.y; acc[2]  += cw * x0.z; acc[3]  += cw * x0.w;
        acc[4]  += cw * x1.x; acc[5]  += cw * x1.y; acc[6]  += cw * x1.z; acc[7]  += cw * x1.w;
        acc[8]  += cw * x2.x; acc[9]  += cw * x2.y; acc[10] += cw * x2.z; acc[11] += cw * x2.w;
        acc[12] += cw * x3.x; acc[13] += cw * x3.y; acc[14] += cw * x3.z; acc[15] += cw * x3.w;
    }
    __shared__ float sh[128][17];
#pragma unroll
    for (int o = 0; o < 16; o++) sh[tid][o] = acc[o];
    __syncthreads();
    for (int st = 64; st > 0; st >>= 1) {
        if (tid < st)
#pragma unroll
            for (int o = 0; o < 16; o++) sh[tid][o] += sh[tid + st][o];
        __syncthreads();
    }
    if (tid < 16) {
        float val = sh[0][tid];
        float sq = val * val;
#pragma unroll
        for (int off = 8; off > 0; off >>= 1)
            sq += __shfl_xor_sync(0xffffu, sq, off);
        float sc = (sq / (1.f + sq)) / sqrtf(sq + 1e-8f);
        vout[(long)bj * 16 + tid] = val * sc;
    }
}

__global__ void route_update_k(const float* __restrict__ xh,
                               const float* __restrict__ v,
                               float* __restrict__ bl, int overwrite)
{
    int bj = blockIdx.x;
    int tid = threadIdx.x;  // 128
    __shared__ float vs[16];
    if (tid < 16) vs[tid] = v[(long)bj * 16 + tid];
    __syncthreads();
    for (int i = tid; i < 1152; i += 128) {
        const float4* xp = (const float4*)(xh + ((long)bj * 1152 + i) * 16);
        float4 x0 = xp[0], x1 = xp[1], x2 = xp[2], x3 = xp[3];
        float d = vs[0]*x0.x + vs[1]*x0.y + vs[2]*x0.z + vs[3]*x0.w
                + vs[4]*x1.x + vs[5]*x1.y + vs[6]*x1.z + vs[7]*x1.w
                + vs[8]*x2.x + vs[9]*x2.y + vs[10]*x2.z + vs[11]*x2.w
                + vs[12]*x3.x + vs[13]*x3.y + vs[14]*x3.z + vs[15]*x3.w;
        long o = (long)bj * 1152 + i;
        bl[o] = overwrite ? d : bl[o] + d;
    }
}

__global__ void softmax_j_k(const float* __restrict__ bl, float* __restrict__ c, int total)
{
    int idx = blockIdx.x * blockDim.x + threadIdx.x;
    if (idx >= total) return;
    int b = idx / 1152, i = idx % 1152;
    const float* p = bl + (long)b * 101 * 1152 + i;
    float mx = p[0];
    for (int j = 1; j < 101; j++) {
        float t = p[(long)j * 1152];
        if (t > mx) mx = t;
    }
    float sum = 0.f;
    for (int j = 0; j < 101; j++) sum += expf(p[(long)j * 1152] - mx);
    float inv = 1.f / sum;
    float* q = c + (long)b * 101 * 1152 + i;
    for (int j = 0; j < 101; j++) q[(long)j * 1152] = expf(p[(long)j * 1152] - mx) * inv;
}

// ---------------------------------------------------------------------------
// Host-side orchestration
// ---------------------------------------------------------------------------
static float* symaddr(const void* sym)
{
    void* p = nullptr;
    cudaGetSymbolAddress(&p, sym);
    return (float*)p;
}

template<int KH, int KW, int SS, int PP>
static void run_convhmma(const float* w, const float* in, const float* bias, float* outp,
                         int M, int C, int H, int Win, int OH, int OW, int relu,
                         u32* packW, u32* packA)
{
    const int K = C * KH * KW;
    const int Kpad = ((K + 31) / 32) * 32;
    const int Mpad = ((M + 127) / 128) * 128;
    u16* whi = (u16*)packW;
    u16* wlo = whi + (size_t)Mpad * Kpad;
    {
        int tot = Mpad * Kpad;
        pack_wsplit_k<<<(tot + 255) / 256, 256>>>(w, whi, wlo, M, K, Kpad, tot);
    }
    {
        int tot = 64 * C * H * Win;
        pack_act_k<<<(tot + 255) / 256, 256>>>(in, packA, tot);
    }
    static bool attr11 = false, attr5 = false, attr3 = false;
    bool& flag = (KH == 11) ? attr11 : (KH == 5) ? attr5 : attr3;
    if (!flag) {
        cudaFuncSetAttribute(convhmma_k<KH, KW, SS, PP>,
                             cudaFuncAttributeMaxDynamicSharedMemorySize, CV_SMEM);
        flag = true;
    }
    int N = 64 * OH * OW;
    dim3 grid((N + 127) / 128, Mpad / 128);
    convhmma_k<KH, KW, SS, PP><<<grid, 256, CV_SMEM>>>(whi, wlo, packA, bias, outp,
                                                       M, C, H, Win, OH, OW, K, Kpad, relu);
}

static void run_gemm64(const float* A, const float* Bm, const float* bias, float* C,
                       int M, int N, int K, int relu)
{
    dim3 grid((N + 63) / 64, (M + 63) / 64);
    gemm64_k<<<grid, 256>>>(A, Bm, bias, C, M, N, K, relu);
}

static void run_maxpool(const float* in, float* out, int C, int H, int W,
                        int OH, int OW, int ks, int stride, int pad)
{
    int total = 64 * C * OH * OW;
    maxpool_k<<<(total + 255) / 256, 256>>>(in, out, C, H, W, OH, OW, ks, stride, pad, total);
}

extern "C" void kernel_launch(void* const* d_in, const int* in_sizes, int n_in,
                              void* d_out, int out_size)
{
    const float* x      = (const float*)d_in[0];
    const float* w1     = (const float*)d_in[1];
    const float* b1     = (const float*)d_in[2];
    const float* w2     = (const float*)d_in[3];
    const float* b2     = (const float*)d_in[4];
    const float* w3     = (const float*)d_in[5];
    const float* b3     = (const float*)d_in[6];
    const float* w4     = (const float*)d_in[7];
    const float* b4     = (const float*)d_in[8];
    const float* w5     = (const float*)d_in[9];
    const float* b5     = (const float*)d_in[10];
    const float* pc_w   = (const float*)d_in[11];
    const float* pc_b   = (const float*)d_in[12];
    const float* caps_W = (const float*)d_in[13];
    const float* fc1_w  = (const float*)d_in[14];
    const float* fc1_b  = (const float*)d_in[15];
    const float* fc2_w  = (const float*)d_in[16];
    const float* fc2_b  = (const float*)d_in[17];
    const float* fc3_w  = (const float*)d_in[18];
    const float* fc3_b  = (const float*)d_in[19];
    float* out = (float*)d_out;

    float* a1  = symaddr(g_a1);
    float* p1  = symaddr(g_p1);
    float* a2  = symaddr(g_a2);
    float* p2  = symaddr(g_p2);
    float* a3  = symaddr(g_a3);
    float* a4  = symaddr(g_a4);
    float* a5  = symaddr(g_a5);
    float* p3  = symaddr(g_p3);
    float* pc  = symaddr(g_pc);
    float* u   = symaddr(g_u);
    float* xh  = symaddr(g_xh);
    float* bl  = symaddr(g_bl);
    float* cc  = symaddr(g_cc);
    float* v   = symaddr(g_v);
    float* f1  = symaddr(g_f1);
    float* f2  = symaddr(g_f2);
    u32* packA = (u32*)symaddr(g_packA);
    u32* packW = (u32*)symaddr(g_packW);

    // ---- conv stack ----
    run_convhmma<11, 11, 4, 0>(w1, x, b1, a1, 96, 3, 227, 227, 55, 55, 1, packW, packA);
    run_maxpool(a1, p1, 96, 55, 55, 27, 27, 3, 2, 0);

    run_convhmma<5, 5, 1, 2>(w2, p1, b2, a2, 256, 96, 27, 27, 27, 27, 1, packW, packA);
    run_maxpool(a2, p2, 256, 27, 27, 14, 14, 3, 2, 1);

    run_convhmma<3, 3, 1, 1>(w3, p2, b3, a3, 384, 256, 14, 14, 14, 14, 1, packW, packA);
    run_convhmma<3, 3, 1, 1>(w4, a3, b4, a4, 384, 384, 14, 14, 14, 14, 1, packW, packA);
    run_convhmma<3, 3, 1, 1>(w5, a4, b5, a5, 256, 384, 14, 14, 14, 14, 1, packW, packA);
    run_maxpool(a5, p3, 256, 14, 14, 6, 6, 3, 2, 0);

    run_convhmma<3, 3, 1, 1>(pc_w, p3, pc_b, pc, 256, 256, 6, 6, 6, 6, 0, packW, packA);

    // squash -> u [64,1152,8]
    squash8_k<<<(64 * 1152 + 255) / 256, 256>>>(pc, u, 64 * 1152);

    // x_hat [64,101,1152,16] (coalesced v2)
    {
        static bool attrx = false;
        if (!attrx) {
            cudaFuncSetAttribute(xhat2_k, cudaFuncAttributeMaxDynamicSharedMemorySize, XH_SMEM);
            attrx = true;
        }
        dim3 g(9, 101);
        xhat2_k<<<g, 128, XH_SMEM>>>(caps_W, u, xh);
    }

    // ---- dynamic routing (3 iterations), squash fused into reduce ----
    const int NBJ = 64 * 101;
    route_reduce_k<<<NBJ, 128>>>(xh, nullptr, v);
    route_update_k<<<NBJ, 128>>>(xh, v, bl, 1);
    softmax_j_k<<<(64 * 1152 + 255) / 256, 256>>>(bl, cc, 64 * 1152);
    route_reduce_k<<<NBJ, 128>>>(xh, cc, v);
    route_update_k<<<NBJ, 128>>>(xh, v, bl, 0);
    softmax_j_k<<<(64 * 1152 + 255) / 256, 256>>>(bl, cc, 64 * 1152);
    route_reduce_k<<<NBJ, 128>>>(xh, cc, v);

    // ---- MLP head ----
    run_gemm64(fc1_w, v, fc1_b, f1, 4096, 64, 1616, 1);
    run_gemm64(fc2_w, f1, fc2_b, f2, 4096, 64, 4096, 1);
    run_gemm64(fc3_w, f2, fc3_b, out, 101, 64, 4096, 0);
}

// round 7
// speedup vs baseline: 1.2856x; 1.2856x over previous
#include <cuda_runtime.h>
#include <math.h>

typedef unsigned int   u32;
typedef unsigned short u16;
typedef unsigned long long ull;

// ---------------------------------------------------------------------------
// Scratch buffers (device globals — allocation-free per harness rules)
// ---------------------------------------------------------------------------
__device__ float g_a1[18585600];     // conv1 out [64,96,55,55]
__device__ float g_p1[4478976];      // pool1     [64,96,27,27]
__device__ float g_a2[11943936];     // conv2 out [64,256,27,27]
__device__ float g_p2[3211264];      // pool2     [64,256,14,14]
__device__ float g_a3[4816896];      // conv3 out [64,384,14,14]
__device__ float g_a4[4816896];      // conv4 out
__device__ float g_a5[3211264];      // conv5 out [64,256,14,14]
__device__ float g_p3[589824];       // pool3     [64,256,6,6]
__device__ float g_pc[589824];       // primarycaps conv out
__device__ float g_u[589824];        // squashed capsules [64,1152,8]
__device__ float g_xh[119144448];    // x_hat [64,101,1152,16]
__device__ float g_bl[7446528];      // b logits [64,101,1152]
__device__ float g_cc[7446528];      // coupling coeffs
__device__ float g_v[103424];        // v [64,101,16]
__device__ float g_f1[262144];       // fc1 out [64,4096]
__device__ float g_f2[262144];       // fc2 out [64,4096]
__device__ u32   g_packA[10000000];  // packed hi|lo activations (per layer)
__device__ u32   g_packW[1400000];   // split weight planes: hi u16[]; lo u16[]

// ---------------------------------------------------------------------------
// bf16 hi/lo split: x ≈ hi + lo (both bf16 RNE). packed u32 = (hi<<16)|lo
// ---------------------------------------------------------------------------
__device__ __forceinline__ u32 pack_hilo(float x)
{
    u32 u  = __float_as_uint(x);
    u32 hi = (u + 0x7fffu + ((u >> 16) & 1u)) >> 16;
    float hf = __uint_as_float(hi << 16);
    u32 v  = __float_as_uint(x - hf);
    u32 lo = (v + 0x7fffu + ((v >> 16) & 1u)) >> 16;
    return (hi << 16) | lo;
}

__global__ void pack_act_k(const float* __restrict__ src, u32* __restrict__ dst, int n)
{
    int i = blockIdx.x * blockDim.x + threadIdx.x;
    if (i < n) dst[i] = pack_hilo(src[i]);
}

__global__ void pack_wsplit_k(const float* __restrict__ src,
                              u16* __restrict__ hi, u16* __restrict__ lo,
                              int M, int K, int Kpad, int tot)
{
    int i = blockIdx.x * blockDim.x + threadIdx.x;
    if (i >= tot) return;
    int m = i / Kpad, k = i - m * Kpad;
    float x = (m < M && k < K) ? src[(long)m * K + k] : 0.f;
    u32 p = pack_hilo(x);
    hi[i] = (u16)(p >> 16);
    lo[i] = (u16)(p & 0xffffu);
}

// ---------------------------------------------------------------------------
// mma.sync bf16 + cp.async helpers
// ---------------------------------------------------------------------------
__device__ __forceinline__ void mma_bf16(float* d, const u32* a, u32 b0, u32 b1)
{
    asm("mma.sync.aligned.m16n8k16.row.col.f32.bf16.bf16.f32 "
        "{%0,%1,%2,%3}, {%4,%5,%6,%7}, {%8,%9}, {%0,%1,%2,%3};"
        : "+f"(d[0]), "+f"(d[1]), "+f"(d[2]), "+f"(d[3])
        : "r"(a[0]), "r"(a[1]), "r"(a[2]), "r"(a[3]), "r"(b0), "r"(b1));
}

__device__ __forceinline__ void cp_async16(u32 dst, const void* src)
{
    asm volatile("cp.async.ca.shared.global [%0], [%1], 16;"
                 :: "r"(dst), "l"(src) : "memory");
}
__device__ __forceinline__ void cp_commit()
{
    asm volatile("cp.async.commit_group;" ::: "memory");
}
template<int N> __device__ __forceinline__ void cp_wait()
{
    asm volatile("cp.async.wait_group %0;" :: "n"(N) : "memory");
}

// ---------------------------------------------------------------------------
// Implicit-GEMM conv on mma.sync bf16, 2-term split (3 passes).
// 128x128 tile, BK=32, 8 warps (4x2), double-buffered smem, 80B row stride
// (conflict-free). NO min-blocks clamp: let ptxas pick registers (round-6
// regression traced to the (256,2) 128-reg cap forcing spills).
// ---------------------------------------------------------------------------
static constexpr int CV_ROWB  = 80;
static constexpr int CV_ARR   = 128 * CV_ROWB;           // 10240
static constexpr int CV_AH = 0, CV_AL = CV_ARR, CV_BH = 2 * CV_ARR, CV_BL = 3 * CV_ARR;
static constexpr int CV_STAGE = 4 * CV_ARR;              // 40960
static constexpr int CV_SMEM  = 2 * CV_STAGE;            // 81920

template<int KH, int KW, int SS, int PP>
__global__ __launch_bounds__(256)
void convhmma_k(const u16* __restrict__ whi, const u16* __restrict__ wlo,
                const u32* __restrict__ pin, const float* __restrict__ bias,
                float* __restrict__ outp,
                int M, int C, int H, int W, int OH, int OW,
                int K, int Kpad, int relu)
{
    extern __shared__ char smem[];
    const u32 sbase = (u32)__cvta_generic_to_shared(smem);

    const int tid  = threadIdx.x;
    const int wid  = tid >> 5, lane = tid & 31;
    const int g    = lane >> 2, qi = lane & 3;
    const int mwarp = (wid >> 1) * 32, nwarp = (wid & 1) * 64;
    const int KHW  = KH * KW;
    const int OHW  = OH * OW;
    const int N    = 64 * OHW;
    const int m0   = blockIdx.y * 128, n0 = blockIdx.x * 128;

    const int lrow = tid & 127;
    const int half = tid >> 7;

    const int gn = n0 + lrow;
    const bool nvalid = gn < N;
    const int bn = nvalid ? gn : 0;
    const int ow = bn % OW;
    const int t1 = bn / OW;
    const int oh = t1 % OH;
    const int bb = t1 / OH;
    const int ihb = oh * SS - PP, iwb = ow * SS - PP;
    const u32* inb = pin + (long)bb * C * H * W;

    const int nstage = Kpad / 32;

    auto issueA = [&](int ck, int buf) {
        const u16* srch = whi + (long)(m0 + lrow) * Kpad + ck * 32 + half * 16;
        const u16* srcl = wlo + (long)(m0 + lrow) * Kpad + ck * 32 + half * 16;
        u32 d = sbase + buf * CV_STAGE + lrow * CV_ROWB + half * 32;
        cp_async16(d + CV_AH,      srch);
        cp_async16(d + CV_AH + 16, srch + 8);
        cp_async16(d + CV_AL,      srcl);
        cp_async16(d + CV_AL + 16, srcl + 8);
        cp_commit();
    };

    u32 breg[16];
    auto loadB = [&](int ck) {
        int gk0 = ck * 32 + half * 16;
        int cc = gk0 / KHW;
        int r  = gk0 - cc * KHW;
        int kh = r / KW;
        int kw = r - kh * KW;
#pragma unroll
        for (int t = 0; t < 16; t++) {
            u32 v = 0u;
            if (nvalid && gk0 + t < K) {
                int ih = ihb + kh, iw = iwb + kw;
                if ((unsigned)ih < (unsigned)H && (unsigned)iw < (unsigned)W)
                    v = inb[((long)cc * H + ih) * W + iw];
            }
            breg[t] = v;
            if (++kw == KW) { kw = 0; if (++kh == KH) { kh = 0; ++cc; } }
        }
    };
    auto storeB = [&](int buf) {
        u32 h[8], l[8];
#pragma unroll
        for (int t = 0; t < 8; t++) {
            h[t] = __byte_perm(breg[2 * t], breg[2 * t + 1], 0x7632);
            l[t] = __byte_perm(breg[2 * t], breg[2 * t + 1], 0x5410);
        }
        char* d = smem + buf * CV_STAGE + lrow * CV_ROWB + half * 32;
        *(uint4*)(d + CV_BH)      = make_uint4(h[0], h[1], h[2], h[3]);
        *(uint4*)(d + CV_BH + 16) = make_uint4(h[4], h[5], h[6], h[7]);
        *(uint4*)(d + CV_BL)      = make_uint4(l[0], l[1], l[2], l[3]);
        *(uint4*)(d + CV_BL + 16) = make_uint4(l[4], l[5], l[6], l[7]);
    };

    float acc[2][8][4];
#pragma unroll
    for (int i = 0; i < 2; i++)
#pragma unroll
        for (int j = 0; j < 8; j++)
#pragma unroll
            for (int q = 0; q < 4; q++) acc[i][j][q] = 0.f;

    int buf = 0;
    issueA(0, 0);
    loadB(0);

    for (int ck = 0; ck < nstage; ck++) {
        storeB(buf);
        cp_wait<0>();
        __syncthreads();
        if (ck + 1 < nstage) {
            issueA(ck + 1, buf ^ 1);
            loadB(ck + 1);
        }

        const char* st = smem + buf * CV_STAGE;
#pragma unroll
        for (int kk = 0; kk < 2; kk++) {
            u32 ah[2][4], al[2][4];
#pragma unroll
            for (int mt = 0; mt < 2; mt++) {
                const char* rA = st + (mwarp + mt * 16 + g) * CV_ROWB + kk * 32 + qi * 4;
                ah[mt][0] = *(const u32*)(rA + CV_AH);
                ah[mt][1] = *(const u32*)(rA + CV_AH + 8 * CV_ROWB);
                ah[mt][2] = *(const u32*)(rA + CV_AH + 16);
                ah[mt][3] = *(const u32*)(rA + CV_AH + 8 * CV_ROWB + 16);
                al[mt][0] = *(const u32*)(rA + CV_AL);
                al[mt][1] = *(const u32*)(rA + CV_AL + 8 * CV_ROWB);
                al[mt][2] = *(const u32*)(rA + CV_AL + 16);
                al[mt][3] = *(const u32*)(rA + CV_AL + 8 * CV_ROWB + 16);
            }
#pragma unroll
            for (int nt = 0; nt < 8; nt++) {
                const char* rB = st + (nwarp + nt * 8 + g) * CV_ROWB + kk * 32 + qi * 4;
                u32 bh0 = *(const u32*)(rB + CV_BH);
                u32 bh1 = *(const u32*)(rB + CV_BH + 16);
                u32 bl0 = *(const u32*)(rB + CV_BL);
                u32 bl1 = *(const u32*)(rB + CV_BL + 16);
                mma_bf16(acc[0][nt], ah[0], bh0, bh1);
                mma_bf16(acc[1][nt], ah[1], bh0, bh1);
                mma_bf16(acc[0][nt], al[0], bh0, bh1);
                mma_bf16(acc[1][nt], al[1], bh0, bh1);
                mma_bf16(acc[0][nt], ah[0], bl0, bl1);
                mma_bf16(acc[1][nt], ah[1], bl0, bl1);
            }
        }
        __syncthreads();
        buf ^= 1;
    }

    // ---- epilogue: bias (+relu) + NCHW scatter
    int colb[16], colp[16];
    bool colok[16];
#pragma unroll
    for (int nt = 0; nt < 8; nt++)
#pragma unroll
        for (int q = 0; q < 2; q++) {
            int ci = nt * 2 + q;
            int n = n0 + nwarp + nt * 8 + 2 * qi + q;
            colok[ci] = n < N;
            int nc = colok[ci] ? n : 0;
            colb[ci] = nc / OHW;
            colp[ci] = nc - colb[ci] * OHW;
        }
#pragma unroll
    for (int mt = 0; mt < 2; mt++) {
        int mA = m0 + mwarp + mt * 16 + g;
        int mB = mA + 8;
        float bvA = (mA < M) ? bias[mA] : 0.f;
        float bvB = (mB < M) ? bias[mB] : 0.f;
#pragma unroll
        for (int nt = 0; nt < 8; nt++)
#pragma unroll
            for (int q = 0; q < 2; q++) {
                int ci = nt * 2 + q;
                if (!colok[ci]) continue;
                long base = ((long)colb[ci] * M) * OHW + colp[ci];
                if (mA < M) {
                    float v = acc[mt][nt][q] + bvA;
                    if (relu && v < 0.f) v = 0.f;
                    outp[base + (long)mA * OHW] = v;
                }
                if (mB < M) {
                    float v = acc[mt][nt][2 + q] + bvB;
                    if (relu && v < 0.f) v = 0.f;
                    outp[base + (long)mB * OHW] = v;
                }
            }
    }
}

// ---------------------------------------------------------------------------
// 64x64-tile f32x2 GEMM (FC layers).  B given [N,K]; C[n*M+m]
// ---------------------------------------------------------------------------
__global__ __launch_bounds__(256, 2) void gemm64_k(
    const float* __restrict__ A, const float* __restrict__ Bm,
    const float* __restrict__ bias, float* __restrict__ Cout,
    int M, int N, int K, int relu)
{
    __shared__ __align__(16) float As[16][64];
    __shared__ __align__(16) float Bs[16][64];

    const int tid = threadIdx.x;
    const int m0 = blockIdx.y * 64, n0 = blockIdx.x * 64;
    const int tx = tid & 15, ty = tid >> 4;
    const int lm = tid & 63;
    const int lk4 = (tid >> 6) * 4;

    ull acc[4][2];
#pragma unroll
    for (int i = 0; i < 4; i++) { acc[i][0] = 0ULL; acc[i][1] = 0ULL; }

    for (int k0 = 0; k0 < K; k0 += 16) {
        {
            int gm = m0 + lm;
            if (gm < M) {
                float4 av = *(const float4*)&A[(long)gm * K + k0 + lk4];
                As[lk4 + 0][lm] = av.x; As[lk4 + 1][lm] = av.y;
                As[lk4 + 2][lm] = av.z; As[lk4 + 3][lm] = av.w;
            } else {
                As[lk4 + 0][lm] = 0.f; As[lk4 + 1][lm] = 0.f;
                As[lk4 + 2][lm] = 0.f; As[lk4 + 3][lm] = 0.f;
            }
        }
        {
            int gn = n0 + lm;
            if (gn < N) {
                float4 bv = *(const float4*)&Bm[(long)gn * K + k0 + lk4];
                Bs[lk4 + 0][lm] = bv.x; Bs[lk4 + 1][lm] = bv.y;
                Bs[lk4 + 2][lm] = bv.z; Bs[lk4 + 3][lm] = bv.w;
            } else {
                Bs[lk4 + 0][lm] = 0.f; Bs[lk4 + 1][lm] = 0.f;
                Bs[lk4 + 2][lm] = 0.f; Bs[lk4 + 3][lm] = 0.f;
            }
        }
        __syncthreads();
#pragma unroll
        for (int kk = 0; kk < 16; kk++) {
            float4 a4 = *(const float4*)&As[kk][ty * 4];
            ulonglong2 bv = *(const ulonglong2*)&Bs[kk][tx * 4];
            ull bp[2] = {bv.x, bv.y};
            float av[4] = {a4.x, a4.y, a4.z, a4.w};
#pragma unroll
            for (int i = 0; i < 4; i++) {
                ull sa;
                asm("mov.b64 %0, {%1, %1};" : "=l"(sa) : "f"(av[i]));
#pragma unroll
                for (int j = 0; j < 2; j++)
                    asm("fma.rn.f32x2 %0, %1, %2, %0;"
                        : "+l"(acc[i][j]) : "l"(sa), "l"(bp[j]));
            }
        }
        __syncthreads();
    }

#pragma unroll
    for (int i = 0; i < 4; i++) {
        int m = m0 + ty * 4 + i;
        if (m >= M) continue;
        float bv = bias ? bias[m] : 0.f;
#pragma unroll
        for (int j = 0; j < 2; j++) {
            float lo, hi;
            asm("mov.b64 {%0, %1}, %2;" : "=f"(lo), "=f"(hi) : "l"(acc[i][j]));
            float v0 = lo + bv, v1 = hi + bv;
            if (relu) { if (v0 < 0.f) v0 = 0.f; if (v1 < 0.f) v1 = 0.f; }
            int nA = n0 + tx * 4 + 2 * j, nB = nA + 1;
            if (nA < N) Cout[(long)nA * M + m] = v0;
            if (nB < N) Cout[(long)nB * M + m] = v1;
        }
    }
}

// ---------------------------------------------------------------------------
// MaxPool (floor mode)
// ---------------------------------------------------------------------------
__global__ void maxpool_k(const float* __restrict__ in, float* __restrict__ out,
                          int C, int H, int W, int OH, int OW,
                          int ks, int stride, int pad, int total)
{
    int idx = blockIdx.x * blockDim.x + threadIdx.x;
    if (idx >= total) return;
    int ow = idx % OW;
    int t = idx / OW;
    int oh = t % OH; t /= OH;
    int c = t % C;
    int b = t / C;
    const float* p = in + (long)(b * C + c) * H * W;
    float mx = -3.4e38f;
    int h0 = oh * stride - pad, w0 = ow * stride - pad;
    for (int kh = 0; kh < ks; kh++) {
        int ih = h0 + kh;
        if (ih < 0 || ih >= H) continue;
        for (int kw = 0; kw < ks; kw++) {
            int iw = w0 + kw;
            if (iw < 0 || iw >= W) continue;
            float v = p[ih * W + iw];
            if (v > mx) mx = v;
        }
    }
    out[idx] = mx;
}

// ---------------------------------------------------------------------------
// squash8 (primary caps)
// ---------------------------------------------------------------------------
__global__ void squash8_k(const float* __restrict__ p, float* __restrict__ u, int ncaps)
{
    int idx = blockIdx.x * blockDim.x + threadIdx.x;
    if (idx >= ncaps) return;
    const float4* ip = (const float4*)(p + (long)idx * 8);
    float4 a = ip[0], b = ip[1];
    float sq = a.x*a.x + a.y*a.y + a.z*a.z + a.w*a.w
             + b.x*b.x + b.y*b.y + b.z*b.z + b.w*b.w;
    float sc = (sq / (1.f + sq)) / sqrtf(sq + 1e-8f);
    float4* op = (float4*)(u + (long)idx * 8);
    op[0] = make_float4(a.x*sc, a.y*sc, a.z*sc, a.w*sc);
    op[1] = make_float4(b.x*sc, b.y*sc, b.z*sc, b.w*sc);
}

// ---------------------------------------------------------------------------
// xhat v2: coalesced.  grid (9, 101), 128 threads.
// ---------------------------------------------------------------------------
static constexpr int XH_SMEM = 128 * 132 * 4;   // 67584

__global__ __launch_bounds__(128) void xhat2_k(
    const float* __restrict__ Wc, const float* __restrict__ u,
    float* __restrict__ xh)
{
    extern __shared__ float Ws[];
    const int j = blockIdx.y, i0 = blockIdx.x * 128, t = threadIdx.x;

    const float* wsrc = Wc + ((long)j * 1152 + i0) * 128;
    for (int idx = t; idx < 128 * 128; idx += 128) {
        int row = idx >> 7, col = idx & 127;
        Ws[row * 132 + col] = wsrc[idx];
    }
    __syncthreads();

    const float* wrow = Ws + t * 132;
    for (int b = 0; b < 64; b++) {
        const float4* up = (const float4*)(u + ((long)b * 1152 + i0 + t) * 8);
        float4 u0 = up[0], u1 = up[1];
        float* op = xh + (((long)b * 101 + j) * 1152 + i0 + t) * 16;
#pragma unroll
        for (int og = 0; og < 4; og++) {
            float o[4];
#pragma unroll
            for (int q = 0; q < 4; q++) {
                const float4* w4 = (const float4*)(wrow + (og * 4 + q) * 8);
                float4 w0 = w4[0], w1 = w4[1];
                o[q] = w0.x*u0.x + w0.y*u0.y + w0.z*u0.z + w0.w*u0.w
                     + w1.x*u1.x + w1.y*u1.y + w1.z*u1.z + w1.w*u1.w;
            }
            ((float4*)op)[og] = make_float4(o[0], o[1], o[2], o[3]);
        }
    }
}

// ---------------------------------------------------------------------------
// routing: reduce + fused squash -> v directly
// ---------------------------------------------------------------------------
__global__ void route_reduce_k(const float* __restrict__ xh,
                               const float* __restrict__ c,
                               float* __restrict__ vout)
{
    int bj = blockIdx.x;
    int tid = threadIdx.x;
    const float* xb = xh + (long)bj * 1152 * 16;
    float acc[16];
#pragma unroll
    for (int o = 0; o < 16; o++) acc[o] = 0.f;
    for (int i = tid; i < 1152; i += 128) {
        float cw = c ? c[(long)bj * 1152 + i] : (1.f / 101.f);
        const float4* xp = (const float4*)(xb + (long)i * 16);
        float4 x0 = xp[0], x1 = xp[1], x2 = xp[2], x3 = xp[3];
        acc[0]  += cw * x0.x; acc[1]  += cw * x0.y; acc[2]  += cw * x0.z; acc[3]  += cw * x0.w;
        acc[4]  += cw * x1.x; acc[5]  += cw * x1.y; acc[6]  += cw * x1.z; acc[7]  += cw * x1.w;
        acc[8]  += cw * x2.x; acc[9]  += cw * x2.y; acc[10] += cw * x2.z; acc[11] += cw * x2.w;
        acc[12] += cw * x3.x; acc[13] += cw * x3.y; acc[14] += cw * x3.z; acc[15] += cw * x3.w;
    }
    __shared__ float sh[128][17];
#pragma unroll
    for (int o = 0; o < 16; o++) sh[tid][o] = acc[o];
    __syncthreads();
    for (int st = 64; st > 0; st >>= 1) {
        if (tid < st)
#pragma unroll
            for (int o = 0; o < 16; o++) sh[tid][o] += sh[tid + st][o];
        __syncthreads();
    }
    if (tid < 16) {
        float val = sh[0][tid];
        float sq = val * val;
#pragma unroll
        for (int off = 8; off > 0; off >>= 1)
            sq += __shfl_xor_sync(0xffffu, sq, off);
        float sc = (sq / (1.f + sq)) / sqrtf(sq + 1e-8f);
        vout[(long)bj * 16 + tid] = val * sc;
    }
}

__global__ void route_update_k(const float* __restrict__ xh,
                               const float* __restrict__ v,
                               float* __restrict__ bl, int overwrite)
{
    int bj = blockIdx.x;
    int tid = threadIdx.x;  // 128
    __shared__ float vs[16];
    if (tid < 16) vs[tid] = v[(long)bj * 16 + tid];
    __syncthreads();
    for (int i = tid; i < 1152; i += 128) {
        const float4* xp = (const float4*)(xh + ((long)bj * 1152 + i) * 16);
        float4 x0 = xp[0], x1 = xp[1], x2 = xp[2], x3 = xp[3];
        float d = vs[0]*x0.x + vs[1]*x0.y + vs[2]*x0.z + vs[3]*x0.w
                + vs[4]*x1.x + vs[5]*x1.y + vs[6]*x1.z + vs[7]*x1.w
                + vs[8]*x2.x + vs[9]*x2.y + vs[10]*x2.z + vs[11]*x2.w
                + vs[12]*x3.x + vs[13]*x3.y + vs[14]*x3.z + vs[15]*x3.w;
        long o = (long)bj * 1152 + i;
        bl[o] = overwrite ? d : bl[o] + d;
    }
}

__global__ void softmax_j_k(const float* __restrict__ bl, float* __restrict__ c, int total)
{
    int idx = blockIdx.x * blockDim.x + threadIdx.x;
    if (idx >= total) return;
    int b = idx / 1152, i = idx % 1152;
    const float* p = bl + (long)b * 101 * 1152 + i;
    float mx = p[0];
    for (int j = 1; j < 101; j++) {
        float t = p[(long)j * 1152];
        if (t > mx) mx = t;
    }
    float sum = 0.f;
    for (int j = 0; j < 101; j++) sum += expf(p[(long)j * 1152] - mx);
    float inv = 1.f / sum;
    float* q = c + (long)b * 101 * 1152 + i;
    for (int j = 0; j < 101; j++) q[(long)j * 1152] = expf(p[(long)j * 1152] - mx) * inv;
}

// ---------------------------------------------------------------------------
// Host-side orchestration
// ---------------------------------------------------------------------------
static float* symaddr(const void* sym)
{
    void* p = nullptr;
    cudaGetSymbolAddress(&p, sym);
    return (float*)p;
}

template<int KH, int KW, int SS, int PP>
static void run_convhmma(const float* w, const float* in, const float* bias, float* outp,
                         int M, int C, int H, int Win, int OH, int OW, int relu,
                         u32* packW, u32* packA)
{
    const int K = C * KH * KW;
    const int Kpad = ((K + 31) / 32) * 32;
    const int Mpad = ((M + 127) / 128) * 128;
    u16* whi = (u16*)packW;
    u16* wlo = whi + (size_t)Mpad * Kpad;
    {
        int tot = Mpad * Kpad;
        pack_wsplit_k<<<(tot + 255) / 256, 256>>>(w, whi, wlo, M, K, Kpad, tot);
    }
    {
        int tot = 64 * C * H * Win;
        pack_act_k<<<(tot + 255) / 256, 256>>>(in, packA, tot);
    }
    static bool attr11 = false, attr5 = false, attr3 = false;
    bool& flag = (KH == 11) ? attr11 : (KH == 5) ? attr5 : attr3;
    if (!flag) {
        cudaFuncSetAttribute(convhmma_k<KH, KW, SS, PP>,
                             cudaFuncAttributeMaxDynamicSharedMemorySize, CV_SMEM);
        flag = true;
    }
    int N = 64 * OH * OW;
    dim3 grid((N + 127) / 128, Mpad / 128);
    convhmma_k<KH, KW, SS, PP><<<grid, 256, CV_SMEM>>>(whi, wlo, packA, bias, outp,
                                                       M, C, H, Win, OH, OW, K, Kpad, relu);
}

static void run_gemm64(const float* A, const float* Bm, const float* bias, float* C,
                       int M, int N, int K, int relu)
{
    dim3 grid((N + 63) / 64, (M + 63) / 64);
    gemm64_k<<<grid, 256>>>(A, Bm, bias, C, M, N, K, relu);
}

static void run_maxpool(const float* in, float* out, int C, int H, int W,
                        int OH, int OW, int ks, int stride, int pad)
{
    int total = 64 * C * OH * OW;
    maxpool_k<<<(total + 255) / 256, 256>>>(in, out, C, H, W, OH, OW, ks, stride, pad, total);
}

extern "C" void kernel_launch(void* const* d_in, const int* in_sizes, int n_in,
                              void* d_out, int out_size)
{
    const float* x      = (const float*)d_in[0];
    const float* w1     = (const float*)d_in[1];
    const float* b1     = (const float*)d_in[2];
    const float* w2     = (const float*)d_in[3];
    const float* b2     = (const float*)d_in[4];
    const float* w3     = (const float*)d_in[5];
    const float* b3     = (const float*)d_in[6];
    const float* w4     = (const float*)d_in[7];
    const float* b4     = (const float*)d_in[8];
    const float* w5     = (const float*)d_in[9];
    const float* b5     = (const float*)d_in[10];
    const float* pc_w   = (const float*)d_in[11];
    const float* pc_b   = (const float*)d_in[12];
    const float* caps_W = (const float*)d_in[13];
    const float* fc1_w  = (const float*)d_in[14];
    const float* fc1_b  = (const float*)d_in[15];
    const float* fc2_w  = (const float*)d_in[16];
    const float* fc2_b  = (const float*)d_in[17];
    const float* fc3_w  = (const float*)d_in[18];
    const float* fc3_b  = (const float*)d_in[19];
    float* out = (float*)d_out;

    float* a1  = symaddr(g_a1);
    float* p1  = symaddr(g_p1);
    float* a2  = symaddr(g_a2);
    float* p2  = symaddr(g_p2);
    float* a3  = symaddr(g_a3);
    float* a4  = symaddr(g_a4);
    float* a5  = symaddr(g_a5);
    float* p3  = symaddr(g_p3);
    float* pc  = symaddr(g_pc);
    float* u   = symaddr(g_u);
    float* xh  = symaddr(g_xh);
    float* bl  = symaddr(g_bl);
    float* cc  = symaddr(g_cc);
    float* v   = symaddr(g_v);
    float* f1  = symaddr(g_f1);
    float* f2  = symaddr(g_f2);
    u32* packA = (u32*)symaddr(g_packA);
    u32* packW = (u32*)symaddr(g_packW);

    // ---- conv stack ----
    run_convhmma<11, 11, 4, 0>(w1, x, b1, a1, 96, 3, 227, 227, 55, 55, 1, packW, packA);
    run_maxpool(a1, p1, 96, 55, 55, 27, 27, 3, 2, 0);

    run_convhmma<5, 5, 1, 2>(w2, p1, b2, a2, 256, 96, 27, 27, 27, 27, 1, packW, packA);
    run_maxpool(a2, p2, 256, 27, 27, 14, 14, 3, 2, 1);

    run_convhmma<3, 3, 1, 1>(w3, p2, b3, a3, 384, 256, 14, 14, 14, 14, 1, packW, packA);
    run_convhmma<3, 3, 1, 1>(w4, a3, b4, a4, 384, 384, 14, 14, 14, 14, 1, packW, packA);
    run_convhmma<3, 3, 1, 1>(w5, a4, b5, a5, 256, 384, 14, 14, 14, 14, 1, packW, packA);
    run_maxpool(a5, p3, 256, 14, 14, 6, 6, 3, 2, 0);

    run_convhmma<3, 3, 1, 1>(pc_w, p3, pc_b, pc, 256, 256, 6, 6, 6, 6, 0, packW, packA);

    // squash -> u [64,1152,8]
    squash8_k<<<(64 * 1152 + 255) / 256, 256>>>(pc, u, 64 * 1152);

    // x_hat [64,101,1152,16]
    {
        static bool attrx = false;
        if (!attrx) {
            cudaFuncSetAttribute(xhat2_k, cudaFuncAttributeMaxDynamicSharedMemorySize, XH_SMEM);
            attrx = true;
        }
        dim3 g(9, 101);
        xhat2_k<<<g, 128, XH_SMEM>>>(caps_W, u, xh);
    }

    // ---- dynamic routing (3 iterations), squash fused into reduce ----
    const int NBJ = 64 * 101;
    route_reduce_k<<<NBJ, 128>>>(xh, nullptr, v);
    route_update_k<<<NBJ, 128>>>(xh, v, bl, 1);
    softmax_j_k<<<(64 * 1152 + 255) / 256, 256>>>(bl, cc, 64 * 1152);
    route_reduce_k<<<NBJ, 128>>>(xh, cc, v);
    route_update_k<<<NBJ, 128>>>(xh, v, bl, 0);
    softmax_j_k<<<(64 * 1152 + 255) / 256, 256>>>(bl, cc, 64 * 1152);
    route_reduce_k<<<NBJ, 128>>>(xh, cc, v);

    // ---- MLP head ----
    run_gemm64(fc1_w, v, fc1_b, f1, 4096, 64, 1616, 1);
    run_gemm64(fc2_w, f1, fc2_b, f2, 4096, 64, 4096, 1);
    run_gemm64(fc3_w, f2, fc3_b, out, 101, 64, 4096, 0);
}

// round 8
// speedup vs baseline: 1.3281x; 1.0330x over previous
#include <cuda_runtime.h>
#include <math.h>

typedef unsigned int   u32;
typedef unsigned short u16;
typedef unsigned long long ull;

// ---------------------------------------------------------------------------
// Scratch buffers (device globals — allocation-free per harness rules)
// ---------------------------------------------------------------------------
__device__ float g_a1[18585600];     // conv1 out [64,96,55,55]
__device__ float g_p1[4478976];      // pool1     [64,96,27,27]
__device__ float g_a2[11943936];     // conv2 out [64,256,27,27]
__device__ float g_p2[3211264];      // pool2     [64,256,14,14]
__device__ float g_a3[4816896];      // conv3 out [64,384,14,14]
__device__ float g_a4[4816896];      // conv4 out
__device__ float g_a5[3211264];      // conv5 out [64,256,14,14]
__device__ float g_p3[589824];       // pool3     [64,256,6,6]
__device__ float g_pc[589824];       // primarycaps conv out
__device__ float g_u[589824];        // squashed capsules [64,1152,8]
__device__ float g_ut[589824];       // transposed capsules [1152,64,8]
__device__ float g_sp[930816];       // partial s [9,64,101,16]
__device__ float g_bl[7446528];      // b logits [101,1152,64]
__device__ float g_cc[7446528];      // coupling coeffs [101,1152,64]
__device__ float g_v[103424];        // v [64,101,16]
__device__ float g_f1[262144];       // fc1 out [64,4096]
__device__ float g_f2[262144];       // fc2 out [64,4096]
__device__ u32   g_packA[10000000];  // packed hi|lo activations (per layer)
__device__ u32   g_packW[1400000];   // split weight planes: hi u16[]; lo u16[]

// ---------------------------------------------------------------------------
// bf16 hi/lo split: x ≈ hi + lo (both bf16 RNE). packed u32 = (hi<<16)|lo
// ---------------------------------------------------------------------------
__device__ __forceinline__ u32 pack_hilo(float x)
{
    u32 u  = __float_as_uint(x);
    u32 hi = (u + 0x7fffu + ((u >> 16) & 1u)) >> 16;
    float hf = __uint_as_float(hi << 16);
    u32 v  = __float_as_uint(x - hf);
    u32 lo = (v + 0x7fffu + ((v >> 16) & 1u)) >> 16;
    return (hi << 16) | lo;
}

__global__ void pack_act_k(const float* __restrict__ src, u32* __restrict__ dst, int n)
{
    int i = blockIdx.x * blockDim.x + threadIdx.x;
    if (i < n) dst[i] = pack_hilo(src[i]);
}

__global__ void pack_wsplit_k(const float* __restrict__ src,
                              u16* __restrict__ hi, u16* __restrict__ lo,
                              int M, int K, int Kpad, int tot)
{
    int i = blockIdx.x * blockDim.x + threadIdx.x;
    if (i >= tot) return;
    int m = i / Kpad, k = i - m * Kpad;
    float x = (m < M && k < K) ? src[(long)m * K + k] : 0.f;
    u32 p = pack_hilo(x);
    hi[i] = (u16)(p >> 16);
    lo[i] = (u16)(p & 0xffffu);
}

// ---------------------------------------------------------------------------
// mma.sync bf16 + cp.async helpers
// ---------------------------------------------------------------------------
__device__ __forceinline__ void mma_bf16(float* d, const u32* a, u32 b0, u32 b1)
{
    asm("mma.sync.aligned.m16n8k16.row.col.f32.bf16.bf16.f32 "
        "{%0,%1,%2,%3}, {%4,%5,%6,%7}, {%8,%9}, {%0,%1,%2,%3};"
        : "+f"(d[0]), "+f"(d[1]), "+f"(d[2]), "+f"(d[3])
        : "r"(a[0]), "r"(a[1]), "r"(a[2]), "r"(a[3]), "r"(b0), "r"(b1));
}

__device__ __forceinline__ void cp_async16(u32 dst, const void* src)
{
    asm volatile("cp.async.ca.shared.global [%0], [%1], 16;"
                 :: "r"(dst), "l"(src) : "memory");
}
__device__ __forceinline__ void cp_commit()
{
    asm volatile("cp.async.commit_group;" ::: "memory");
}
template<int N> __device__ __forceinline__ void cp_wait()
{
    asm volatile("cp.async.wait_group %0;" :: "n"(N) : "memory");
}

// ---------------------------------------------------------------------------
// Implicit-GEMM conv on mma.sync bf16, 2-term split (3 passes).
// 128x128 tile, BK=32, 8 warps (4x2), double-buffered smem, 80B row stride.
// NO min-blocks clamp (round-6 regression: reg cap forced spills).
// ---------------------------------------------------------------------------
static constexpr int CV_ROWB  = 80;
static constexpr int CV_ARR   = 128 * CV_ROWB;           // 10240
static constexpr int CV_AH = 0, CV_AL = CV_ARR, CV_BH = 2 * CV_ARR, CV_BL = 3 * CV_ARR;
static constexpr int CV_STAGE = 4 * CV_ARR;              // 40960
static constexpr int CV_SMEM  = 2 * CV_STAGE;            // 81920

template<int KH, int KW, int SS, int PP>
__global__ __launch_bounds__(256)
void convhmma_k(const u16* __restrict__ whi, const u16* __restrict__ wlo,
                const u32* __restrict__ pin, const float* __restrict__ bias,
                float* __restrict__ outp,
                int M, int C, int H, int W, int OH, int OW,
                int K, int Kpad, int relu)
{
    extern __shared__ char smem[];
    const u32 sbase = (u32)__cvta_generic_to_shared(smem);

    const int tid  = threadIdx.x;
    const int wid  = tid >> 5, lane = tid & 31;
    const int g    = lane >> 2, qi = lane & 3;
    const int mwarp = (wid >> 1) * 32, nwarp = (wid & 1) * 64;
    const int KHW  = KH * KW;
    const int OHW  = OH * OW;
    const int N    = 64 * OHW;
    const int m0   = blockIdx.y * 128, n0 = blockIdx.x * 128;

    const int lrow = tid & 127;
    const int half = tid >> 7;

    const int gn = n0 + lrow;
    const bool nvalid = gn < N;
    const int bn = nvalid ? gn : 0;
    const int ow = bn % OW;
    const int t1 = bn / OW;
    const int oh = t1 % OH;
    const int bb = t1 / OH;
    const int ihb = oh * SS - PP, iwb = ow * SS - PP;
    const u32* inb = pin + (long)bb * C * H * W;

    const int nstage = Kpad / 32;

    auto issueA = [&](int ck, int buf) {
        const u16* srch = whi + (long)(m0 + lrow) * Kpad + ck * 32 + half * 16;
        const u16* srcl = wlo + (long)(m0 + lrow) * Kpad + ck * 32 + half * 16;
        u32 d = sbase + buf * CV_STAGE + lrow * CV_ROWB + half * 32;
        cp_async16(d + CV_AH,      srch);
        cp_async16(d + CV_AH + 16, srch + 8);
        cp_async16(d + CV_AL,      srcl);
        cp_async16(d + CV_AL + 16, srcl + 8);
        cp_commit();
    };

    u32 breg[16];
    auto loadB = [&](int ck) {
        int gk0 = ck * 32 + half * 16;
        int cc = gk0 / KHW;
        int r  = gk0 - cc * KHW;
        int kh = r / KW;
        int kw = r - kh * KW;
#pragma unroll
        for (int t = 0; t < 16; t++) {
            u32 v = 0u;
            if (nvalid && gk0 + t < K) {
                int ih = ihb + kh, iw = iwb + kw;
                if ((unsigned)ih < (unsigned)H && (unsigned)iw < (unsigned)W)
                    v = inb[((long)cc * H + ih) * W + iw];
            }
            breg[t] = v;
            if (++kw == KW) { kw = 0; if (++kh == KH) { kh = 0; ++cc; } }
        }
    };
    auto storeB = [&](int buf) {
        u32 h[8], l[8];
#pragma unroll
        for (int t = 0; t < 8; t++) {
            h[t] = __byte_perm(breg[2 * t], breg[2 * t + 1], 0x7632);
            l[t] = __byte_perm(breg[2 * t], breg[2 * t + 1], 0x5410);
        }
        char* d = smem + buf * CV_STAGE + lrow * CV_ROWB + half * 32;
        *(uint4*)(d + CV_BH)      = make_uint4(h[0], h[1], h[2], h[3]);
        *(uint4*)(d + CV_BH + 16) = make_uint4(h[4], h[5], h[6], h[7]);
        *(uint4*)(d + CV_BL)      = make_uint4(l[0], l[1], l[2], l[3]);
        *(uint4*)(d + CV_BL + 16) = make_uint4(l[4], l[5], l[6], l[7]);
    };

    float acc[2][8][4];
#pragma unroll
    for (int i = 0; i < 2; i++)
#pragma unroll
        for (int j = 0; j < 8; j++)
#pragma unroll
            for (int q = 0; q < 4; q++) acc[i][j][q] = 0.f;

    int buf = 0;
    issueA(0, 0);
    loadB(0);

    for (int ck = 0; ck < nstage; ck++) {
        storeB(buf);
        cp_wait<0>();
        __syncthreads();
        if (ck + 1 < nstage) {
            issueA(ck + 1, buf ^ 1);
            loadB(ck + 1);
        }

        const char* st = smem + buf * CV_STAGE;
#pragma unroll
        for (int kk = 0; kk < 2; kk++) {
            u32 ah[2][4], al[2][4];
#pragma unroll
            for (int mt = 0; mt < 2; mt++) {
                const char* rA = st + (mwarp + mt * 16 + g) * CV_ROWB + kk * 32 + qi * 4;
                ah[mt][0] = *(const u32*)(rA + CV_AH);
                ah[mt][1] = *(const u32*)(rA + CV_AH + 8 * CV_ROWB);
                ah[mt][2] = *(const u32*)(rA + CV_AH + 16);
                ah[mt][3] = *(const u32*)(rA + CV_AH + 8 * CV_ROWB + 16);
                al[mt][0] = *(const u32*)(rA + CV_AL);
                al[mt][1] = *(const u32*)(rA + CV_AL + 8 * CV_ROWB);
                al[mt][2] = *(const u32*)(rA + CV_AL + 16);
                al[mt][3] = *(const u32*)(rA + CV_AL + 8 * CV_ROWB + 16);
            }
#pragma unroll
            for (int nt = 0; nt < 8; nt++) {
                const char* rB = st + (nwarp + nt * 8 + g) * CV_ROWB + kk * 32 + qi * 4;
                u32 bh0 = *(const u32*)(rB + CV_BH);
                u32 bh1 = *(const u32*)(rB + CV_BH + 16);
                u32 bl0 = *(const u32*)(rB + CV_BL);
                u32 bl1 = *(const u32*)(rB + CV_BL + 16);
                mma_bf16(acc[0][nt], ah[0], bh0, bh1);
                mma_bf16(acc[1][nt], ah[1], bh0, bh1);
                mma_bf16(acc[0][nt], al[0], bh0, bh1);
                mma_bf16(acc[1][nt], al[1], bh0, bh1);
                mma_bf16(acc[0][nt], ah[0], bl0, bl1);
                mma_bf16(acc[1][nt], ah[1], bl0, bl1);
            }
        }
        __syncthreads();
        buf ^= 1;
    }

    // ---- epilogue: bias (+relu) + NCHW scatter
    int colb[16], colp[16];
    bool colok[16];
#pragma unroll
    for (int nt = 0; nt < 8; nt++)
#pragma unroll
        for (int q = 0; q < 2; q++) {
            int ci = nt * 2 + q;
            int n = n0 + nwarp + nt * 8 + 2 * qi + q;
            colok[ci] = n < N;
            int nc = colok[ci] ? n : 0;
            colb[ci] = nc / OHW;
            colp[ci] = nc - colb[ci] * OHW;
        }
#pragma unroll
    for (int mt = 0; mt < 2; mt++) {
        int mA = m0 + mwarp + mt * 16 + g;
        int mB = mA + 8;
        float bvA = (mA < M) ? bias[mA] : 0.f;
        float bvB = (mB < M) ? bias[mB] : 0.f;
#pragma unroll
        for (int nt = 0; nt < 8; nt++)
#pragma unroll
            for (int q = 0; q < 2; q++) {
                int ci = nt * 2 + q;
                if (!colok[ci]) continue;
                long base = ((long)colb[ci] * M) * OHW + colp[ci];
                if (mA < M) {
                    float v = acc[mt][nt][q] + bvA;
                    if (relu && v < 0.f) v = 0.f;
                    outp[base + (long)mA * OHW] = v;
                }
                if (mB < M) {
                    float v = acc[mt][nt][2 + q] + bvB;
                    if (relu && v < 0.f) v = 0.f;
                    outp[base + (long)mB * OHW] = v;
                }
            }
    }
}

// ---------------------------------------------------------------------------
// 64x64-tile f32x2 GEMM (FC layers).  B given [N,K]; C[n*M+m]
// ---------------------------------------------------------------------------
__global__ __launch_bounds__(256, 2) void gemm64_k(
    const float* __restrict__ A, const float* __restrict__ Bm,
    const float* __restrict__ bias, float* __restrict__ Cout,
    int M, int N, int K, int relu)
{
    __shared__ __align__(16) float As[16][64];
    __shared__ __align__(16) float Bs[16][64];

    const int tid = threadIdx.x;
    const int m0 = blockIdx.y * 64, n0 = blockIdx.x * 64;
    const int tx = tid & 15, ty = tid >> 4;
    const int lm = tid & 63;
    const int lk4 = (tid >> 6) * 4;

    ull acc[4][2];
#pragma unroll
    for (int i = 0; i < 4; i++) { acc[i][0] = 0ULL; acc[i][1] = 0ULL; }

    for (int k0 = 0; k0 < K; k0 += 16) {
        {
            int gm = m0 + lm;
            if (gm < M) {
                float4 av = *(const float4*)&A[(long)gm * K + k0 + lk4];
                As[lk4 + 0][lm] = av.x; As[lk4 + 1][lm] = av.y;
                As[lk4 + 2][lm] = av.z; As[lk4 + 3][lm] = av.w;
            } else {
                As[lk4 + 0][lm] = 0.f; As[lk4 + 1][lm] = 0.f;
                As[lk4 + 2][lm] = 0.f; As[lk4 + 3][lm] = 0.f;
            }
        }
        {
            int gn = n0 + lm;
            if (gn < N) {
                float4 bv = *(const float4*)&Bm[(long)gn * K + k0 + lk4];
                Bs[lk4 + 0][lm] = bv.x; Bs[lk4 + 1][lm] = bv.y;
                Bs[lk4 + 2][lm] = bv.z; Bs[lk4 + 3][lm] = bv.w;
            } else {
                Bs[lk4 + 0][lm] = 0.f; Bs[lk4 + 1][lm] = 0.f;
                Bs[lk4 + 2][lm] = 0.f; Bs[lk4 + 3][lm] = 0.f;
            }
        }
        __syncthreads();
#pragma unroll
        for (int kk = 0; kk < 16; kk++) {
            float4 a4 = *(const float4*)&As[kk][ty * 4];
            ulonglong2 bv = *(const ulonglong2*)&Bs[kk][tx * 4];
            ull bp[2] = {bv.x, bv.y};
            float av[4] = {a4.x, a4.y, a4.z, a4.w};
#pragma unroll
            for (int i = 0; i < 4; i++) {
                ull sa;
                asm("mov.b64 %0, {%1, %1};" : "=l"(sa) : "f"(av[i]));
#pragma unroll
                for (int j = 0; j < 2; j++)
                    asm("fma.rn.f32x2 %0, %1, %2, %0;"
                        : "+l"(acc[i][j]) : "l"(sa), "l"(bp[j]));
            }
        }
        __syncthreads();
    }

#pragma unroll
    for (int i = 0; i < 4; i++) {
        int m = m0 + ty * 4 + i;
        if (m >= M) continue;
        float bv = bias ? bias[m] : 0.f;
#pragma unroll
        for (int j = 0; j < 2; j++) {
            float lo, hi;
            asm("mov.b64 {%0, %1}, %2;" : "=f"(lo), "=f"(hi) : "l"(acc[i][j]));
            float v0 = lo + bv, v1 = hi + bv;
            if (relu) { if (v0 < 0.f) v0 = 0.f; if (v1 < 0.f) v1 = 0.f; }
            int nA = n0 + tx * 4 + 2 * j, nB = nA + 1;
            if (nA < N) Cout[(long)nA * M + m] = v0;
            if (nB < N) Cout[(long)nB * M + m] = v1;
        }
    }
}

// ---------------------------------------------------------------------------
// MaxPool (floor mode)
// ---------------------------------------------------------------------------
__global__ void maxpool_k(const float* __restrict__ in, float* __restrict__ out,
                          int C, int H, int W, int OH, int OW,
                          int ks, int stride, int pad, int total)
{
    int idx = blockIdx.x * blockDim.x + threadIdx.x;
    if (idx >= total) return;
    int ow = idx % OW;
    int t = idx / OW;
    int oh = t % OH; t /= OH;
    int c = t % C;
    int b = t / C;
    const float* p = in + (long)(b * C + c) * H * W;
    float mx = -3.4e38f;
    int h0 = oh * stride - pad, w0 = ow * stride - pad;
    for (int kh = 0; kh < ks; kh++) {
        int ih = h0 + kh;
        if (ih < 0 || ih >= H) continue;
        for (int kw = 0; kw < ks; kw++) {
            int iw = w0 + kw;
            if (iw < 0 || iw >= W) continue;
            float v = p[ih * W + iw];
            if (v > mx) mx = v;
        }
    }
    out[idx] = mx;
}

// ---------------------------------------------------------------------------
// squash8 (primary caps) -> u [64][1152][8]
// ---------------------------------------------------------------------------
__global__ void squash8_k(const float* __restrict__ p, float* __restrict__ u, int ncaps)
{
    int idx = blockIdx.x * blockDim.x + threadIdx.x;
    if (idx >= ncaps) return;
    const float4* ip = (const float4*)(p + (long)idx * 8);
    float4 a = ip[0], b = ip[1];
    float sq = a.x*a.x + a.y*a.y + a.z*a.z + a.w*a.w
             + b.x*b.x + b.y*b.y + b.z*b.z + b.w*b.w;
    float sc = (sq / (1.f + sq)) / sqrtf(sq + 1e-8f);
    float4* op = (float4*)(u + (long)idx * 8);
    op[0] = make_float4(a.x*sc, a.y*sc, a.z*sc, a.w*sc);
    op[1] = make_float4(b.x*sc, b.y*sc, b.z*sc, b.w*sc);
}

// ---------------------------------------------------------------------------
// u transpose: ut[i][b][8] = u[b][i][8]
// ---------------------------------------------------------------------------
__global__ void ut_k(const float* __restrict__ u, float* __restrict__ ut)
{
    int idx = blockIdx.x * blockDim.x + threadIdx.x;   // 73728
    if (idx >= 73728) return;
    int i = idx >> 6, b = idx & 63;
    const float4* src = (const float4*)(u + ((long)b * 1152 + i) * 8);
    float4 a0 = src[0], a1 = src[1];
    float4* dst = (float4*)(ut + (long)idx * 8);
    dst[0] = a0; dst[1] = a1;
}

// ---------------------------------------------------------------------------
// Fused routing — x_hat recomputed on the fly from W (L2-resident) + u.
// fr_k: partial s[p][b][j][o] = sum_{i in chunk p} c[b,j,i] * (W[j,i]·u[b,i])
// grid (9, 101), block 256 = (4 i-subs x 64 batch). W chunk in smem, d-major
// for packed f32x2 inner loop.
// ---------------------------------------------------------------------------
static constexpr int FR_SMEM = 16384 * 4 + 4 * 64 * 17 * 4;   // 82944
static constexpr int FU_SMEM = 16384 * 4;                     // 65536

__global__ __launch_bounds__(256) void fr_k(
    const float* __restrict__ Wc, const float* __restrict__ ut,
    const float* __restrict__ cct, float* __restrict__ sp)
{
    extern __shared__ float sm[];
    float* Wsm = sm;                 // 16384 floats, rows d-major [il][d*16+o]
    float* red = sm + 16384;         // 4*64*17
    const int tid = threadIdx.x;
    const int p = blockIdx.x, j = blockIdx.y;
    const int i0 = p * 128;
    const int s = tid >> 6, b = tid & 63;

    const float* wsrc = Wc + ((long)j * 1152 + i0) * 128;
    for (int idx = tid; idx < 16384; idx += 256) {
        int row = idx >> 7, r = idx & 127;
        Wsm[row * 128 + (r & 7) * 16 + (r >> 3)] = wsrc[idx];
    }
    __syncthreads();

    ull accp[8];
#pragma unroll
    for (int op = 0; op < 8; op++) accp[op] = 0ULL;

    for (int k = 0; k < 32; k++) {
        const int il = s + 4 * k;
        const int i = i0 + il;
        const float4* up = (const float4*)(ut + ((long)i * 64 + b) * 8);
        float4 u0 = up[0], u1 = up[1];
        float ud[8] = {u0.x, u0.y, u0.z, u0.w, u1.x, u1.y, u1.z, u1.w};
        float cw = cct ? cct[((long)j * 1152 + i) * 64 + b] : (1.f / 101.f);
        const float* wr = Wsm + il * 128;
        ull xp[8];
#pragma unroll
        for (int op = 0; op < 8; op++) xp[op] = 0ULL;
#pragma unroll
        for (int d = 0; d < 8; d++) {
            ull us;
            asm("mov.b64 %0, {%1, %1};" : "=l"(us) : "f"(ud[d]));
            const ulonglong2* wp2 = (const ulonglong2*)(wr + d * 16);
#pragma unroll
            for (int q = 0; q < 4; q++) {
                ulonglong2 wv = wp2[q];
                asm("fma.rn.f32x2 %0, %1, %2, %0;" : "+l"(xp[2*q])   : "l"(us), "l"(wv.x));
                asm("fma.rn.f32x2 %0, %1, %2, %0;" : "+l"(xp[2*q+1]) : "l"(us), "l"(wv.y));
            }
        }
        ull cws;
        asm("mov.b64 %0, {%1, %1};" : "=l"(cws) : "f"(cw));
#pragma unroll
        for (int op = 0; op < 8; op++)
            asm("fma.rn.f32x2 %0, %1, %2, %0;" : "+l"(accp[op]) : "l"(cws), "l"(xp[op]));
    }

    float* rr = red + (s * 64 + b) * 17;
#pragma unroll
    for (int op = 0; op < 8; op++) {
        float lo, hi;
        asm("mov.b64 {%0, %1}, %2;" : "=f"(lo), "=f"(hi) : "l"(accp[op]));
        rr[2 * op] = lo; rr[2 * op + 1] = hi;
    }
    __syncthreads();
    for (int t = tid; t < 1024; t += 256) {
        int ob = t >> 4, oo = t & 15;
        float sum = red[(ob) * 17 + oo] + red[(64 + ob) * 17 + oo]
                  + red[(128 + ob) * 17 + oo] + red[(192 + ob) * 17 + oo];
        sp[(((long)p * 64 + ob) * 101 + j) * 16 + oo] = sum;
    }
}

// combine 9 partials + squash -> v [b][j][o]
__global__ void fs_k(const float* __restrict__ sp, float* __restrict__ vout, int total)
{
    int idx = blockIdx.x * blockDim.x + threadIdx.x;
    if (idx >= total) return;               // 103424
    float sum = 0.f;
#pragma unroll
    for (int p = 0; p < 9; p++) sum += sp[(long)p * 103424 + idx];
    float sq = sum * sum;
#pragma unroll
    for (int off = 8; off > 0; off >>= 1)
        sq += __shfl_xor_sync(0xffffffffu, sq, off, 16);
    float sc = (sq / (1.f + sq)) / sqrtf(sq + 1e-8f);
    vout[idx] = sum * sc;
}

// fu_k: bl[j][i][b] (+)= sum_o v[b,j,o] * (W[j,i]·u[b,i])_o
__global__ __launch_bounds__(256) void fu_k(
    const float* __restrict__ Wc, const float* __restrict__ ut,
    const float* __restrict__ v, float* __restrict__ bl, int overwrite)
{
    extern __shared__ float sm[];
    float* Wsm = sm;
    const int tid = threadIdx.x;
    const int p = blockIdx.x, j = blockIdx.y;
    const int i0 = p * 128;
    const int s = tid >> 6, b = tid & 63;

    const float* wsrc = Wc + ((long)j * 1152 + i0) * 128;
    for (int idx = tid; idx < 16384; idx += 256) {
        int row = idx >> 7, r = idx & 127;
        Wsm[row * 128 + (r & 7) * 16 + (r >> 3)] = wsrc[idx];
    }
    __syncthreads();

    ull vp[8];
    const ull* vptr = (const ull*)(v + ((long)b * 101 + j) * 16);
#pragma unroll
    for (int op = 0; op < 8; op++) vp[op] = vptr[op];

    for (int k = 0; k < 32; k++) {
        const int il = s + 4 * k;
        const int i = i0 + il;
        const float4* up = (const float4*)(ut + ((long)i * 64 + b) * 8);
        float4 u0 = up[0], u1 = up[1];
        float ud[8] = {u0.x, u0.y, u0.z, u0.w, u1.x, u1.y, u1.z, u1.w};
        const float* wr = Wsm + il * 128;
        ull xp[8];
#pragma unroll
        for (int op = 0; op < 8; op++) xp[op] = 0ULL;
#pragma unroll
        for (int d = 0; d < 8; d++) {
            ull us;
            asm("mov.b64 %0, {%1, %1};" : "=l"(us) : "f"(ud[d]));
            const ulonglong2* wp2 = (const ulonglong2*)(wr + d * 16);
#pragma unroll
            for (int q = 0; q < 4; q++) {
                ulonglong2 wv = wp2[q];
                asm("fma.rn.f32x2 %0, %1, %2, %0;" : "+l"(xp[2*q])   : "l"(us), "l"(wv.x));
                asm("fma.rn.f32x2 %0, %1, %2, %0;" : "+l"(xp[2*q+1]) : "l"(us), "l"(wv.y));
            }
        }
        ull dp = 0ULL;
#pragma unroll
        for (int op = 0; op < 8; op++)
            asm("fma.rn.f32x2 %0, %1, %2, %0;" : "+l"(dp) : "l"(vp[op]), "l"(xp[op]));
        float lo, hi;
        asm("mov.b64 {%0, %1}, %2;" : "=f"(lo), "=f"(hi) : "l"(dp));
        float d = lo + hi;
        long addr = ((long)j * 1152 + i) * 64 + b;
        bl[addr] = overwrite ? d : bl[addr] + d;
    }
}

// softmax over j for each (i,b); bl/cct layout [j][1152][64]
__global__ void softmax_t_k(const float* __restrict__ bl, float* __restrict__ cct, int total)
{
    int idx = blockIdx.x * blockDim.x + threadIdx.x;
    if (idx >= total) return;    // 73728 = 1152*64
    const float* p = bl + idx;
    float mx = p[0];
    for (int j = 1; j < 101; j++) {
        float t = p[(long)j * 73728];
        if (t > mx) mx = t;
    }
    float sum = 0.f;
    for (int j = 0; j < 101; j++) sum += expf(p[(long)j * 73728] - mx);
    float inv = 1.f / sum;
    float* q = cct + idx;
    for (int j = 0; j < 101; j++) q[(long)j * 73728] = expf(p[(long)j * 73728] - mx) * inv;
}

// ---------------------------------------------------------------------------
// Host-side orchestration
// ---------------------------------------------------------------------------
static float* symaddr(const void* sym)
{
    void* p = nullptr;
    cudaGetSymbolAddress(&p, sym);
    return (float*)p;
}

template<int KH, int KW, int SS, int PP>
static void run_convhmma(const float* w, const float* in, const float* bias, float* outp,
                         int M, int C, int H, int Win, int OH, int OW, int relu,
                         u32* packW, u32* packA)
{
    const int K = C * KH * KW;
    const int Kpad = ((K + 31) / 32) * 32;
    const int Mpad = ((M + 127) / 128) * 128;
    u16* whi = (u16*)packW;
    u16* wlo = whi + (size_t)Mpad * Kpad;
    {
        int tot = Mpad * Kpad;
        pack_wsplit_k<<<(tot + 255) / 256, 256>>>(w, whi, wlo, M, K, Kpad, tot);
    }
    {
        int tot = 64 * C * H * Win;
        pack_act_k<<<(tot + 255) / 256, 256>>>(in, packA, tot);
    }
    static bool attr11 = false, attr5 = false, attr3 = false;
    bool& flag = (KH == 11) ? attr11 : (KH == 5) ? attr5 : attr3;
    if (!flag) {
        cudaFuncSetAttribute(convhmma_k<KH, KW, SS, PP>,
                             cudaFuncAttributeMaxDynamicSharedMemorySize, CV_SMEM);
        flag = true;
    }
    int N = 64 * OH * OW;
    dim3 grid((N + 127) / 128, Mpad / 128);
    convhmma_k<KH, KW, SS, PP><<<grid, 256, CV_SMEM>>>(whi, wlo, packA, bias, outp,
                                                       M, C, H, Win, OH, OW, K, Kpad, relu);
}

static void run_gemm64(const float* A, const float* Bm, const float* bias, float* C,
                       int M, int N, int K, int relu)
{
    dim3 grid((N + 63) / 64, (M + 63) / 64);
    gemm64_k<<<grid, 256>>>(A, Bm, bias, C, M, N, K, relu);
}

static void run_maxpool(const float* in, float* out, int C, int H, int W,
                        int OH, int OW, int ks, int stride, int pad)
{
    int total = 64 * C * OH * OW;
    maxpool_k<<<(total + 255) / 256, 256>>>(in, out, C, H, W, OH, OW, ks, stride, pad, total);
}

extern "C" void kernel_launch(void* const* d_in, const int* in_sizes, int n_in,
                              void* d_out, int out_size)
{
    const float* x      = (const float*)d_in[0];
    const float* w1     = (const float*)d_in[1];
    const float* b1     = (const float*)d_in[2];
    const float* w2     = (const float*)d_in[3];
    const float* b2     = (const float*)d_in[4];
    const float* w3     = (const float*)d_in[5];
    const float* b3     = (const float*)d_in[6];
    const float* w4     = (const float*)d_in[7];
    const float* b4     = (const float*)d_in[8];
    const float* w5     = (const float*)d_in[9];
    const float* b5     = (const float*)d_in[10];
    const float* pc_w   = (const float*)d_in[11];
    const float* pc_b   = (const float*)d_in[12];
    const float* caps_W = (const float*)d_in[13];
    const float* fc1_w  = (const float*)d_in[14];
    const float* fc1_b  = (const float*)d_in[15];
    const float* fc2_w  = (const float*)d_in[16];
    const float* fc2_b  = (const float*)d_in[17];
    const float* fc3_w  = (const float*)d_in[18];
    const float* fc3_b  = (const float*)d_in[19];
    float* out = (float*)d_out;

    float* a1  = symaddr(g_a1);
    float* p1  = symaddr(g_p1);
    float* a2  = symaddr(g_a2);
    float* p2  = symaddr(g_p2);
    float* a3  = symaddr(g_a3);
    float* a4  = symaddr(g_a4);
    float* a5  = symaddr(g_a5);
    float* p3  = symaddr(g_p3);
    float* pc  = symaddr(g_pc);
    float* u   = symaddr(g_u);
    float* ut  = symaddr(g_ut);
    float* sp  = symaddr(g_sp);
    float* bl  = symaddr(g_bl);
    float* cc  = symaddr(g_cc);
    float* v   = symaddr(g_v);
    float* f1  = symaddr(g_f1);
    float* f2  = symaddr(g_f2);
    u32* packA = (u32*)symaddr(g_packA);
    u32* packW = (u32*)symaddr(g_packW);

    // ---- conv stack ----
    run_convhmma<11, 11, 4, 0>(w1, x, b1, a1, 96, 3, 227, 227, 55, 55, 1, packW, packA);
    run_maxpool(a1, p1, 96, 55, 55, 27, 27, 3, 2, 0);

    run_convhmma<5, 5, 1, 2>(w2, p1, b2, a2, 256, 96, 27, 27, 27, 27, 1, packW, packA);
    run_maxpool(a2, p2, 256, 27, 27, 14, 14, 3, 2, 1);

    run_convhmma<3, 3, 1, 1>(w3, p2, b3, a3, 384, 256, 14, 14, 14, 14, 1, packW, packA);
    run_convhmma<3, 3, 1, 1>(w4, a3, b4, a4, 384, 384, 14, 14, 14, 14, 1, packW, packA);
    run_convhmma<3, 3, 1, 1>(w5, a4, b5, a5, 256, 384, 14, 14, 14, 14, 1, packW, packA);
    run_maxpool(a5, p3, 256, 14, 14, 6, 6, 3, 2, 0);

    run_convhmma<3, 3, 1, 1>(pc_w, p3, pc_b, pc, 256, 256, 6, 6, 6, 6, 0, packW, packA);

    // squash -> u [64,1152,8]; transpose -> ut [1152,64,8]
    squash8_k<<<(64 * 1152 + 255) / 256, 256>>>(pc, u, 64 * 1152);
    ut_k<<<288, 256>>>(u, ut);

    // ---- fused dynamic routing (x_hat never materialized) ----
    {
        static bool attrr = false;
        if (!attrr) {
            cudaFuncSetAttribute(fr_k, cudaFuncAttributeMaxDynamicSharedMemorySize, FR_SMEM);
            cudaFuncSetAttribute(fu_k, cudaFuncAttributeMaxDynamicSharedMemorySize, FU_SMEM);
            attrr = true;
        }
        dim3 rg(9, 101);
        // iter 0 (c uniform)
        fr_k<<<rg, 256, FR_SMEM>>>(caps_W, ut, nullptr, sp);
        fs_k<<<404, 256>>>(sp, v, 103424);
        fu_k<<<rg, 256, FU_SMEM>>>(caps_W, ut, v, bl, 1);
        softmax_t_k<<<288, 256>>>(bl, cc, 73728);
        // iter 1
        fr_k<<<rg, 256, FR_SMEM>>>(caps_W, ut, cc, sp);
        fs_k<<<404, 256>>>(sp, v, 103424);
        fu_k<<<rg, 256, FU_SMEM>>>(caps_W, ut, v, bl, 0);
        softmax_t_k<<<288, 256>>>(bl, cc, 73728);
        // iter 2 (final)
        fr_k<<<rg, 256, FR_SMEM>>>(caps_W, ut, cc, sp);
        fs_k<<<404, 256>>>(sp, v, 103424);
    }

    // ---- MLP head ----
    run_gemm64(fc1_w, v, fc1_b, f1, 4096, 64, 1616, 1);
    run_gemm64(fc2_w, f1, fc2_b, f2, 4096, 64, 4096, 1);
    run_gemm64(fc3_w, f2, fc3_b, out, 101, 64, 4096, 0);
}

// round 9
// speedup vs baseline: 1.4542x; 1.0949x over previous
#include <cuda_runtime.h>
#include <math.h>

typedef unsigned int   u32;
typedef unsigned short u16;
typedef unsigned long long ull;

// ---------------------------------------------------------------------------
// Scratch buffers (device globals — allocation-free per harness rules)
// ---------------------------------------------------------------------------
__device__ float g_a1[18585600];     // conv1 out [64,96,55,55]
__device__ float g_p1[4478976];      // pool1     [64,96,27,27]
__device__ float g_a2[11943936];     // conv2 out [64,256,27,27]
__device__ float g_p2[3211264];      // pool2     [64,256,14,14]
__device__ float g_a3[4816896];      // conv3 out [64,384,14,14]
__device__ float g_a4[4816896];      // conv4 out
__device__ float g_a5[3211264];      // conv5 out [64,256,14,14]
__device__ float g_p3[589824];       // pool3     [64,256,6,6]
__device__ float g_pc[589824];       // primarycaps conv out
__device__ float g_u[589824];        // squashed capsules [64,1152,8]
__device__ float g_ut[589824];       // transposed capsules [1152,64,8]
__device__ float g_sp[930816];       // partial s [9,64,101,16]
__device__ float g_bl[7446528];      // b logits [101,1152,64]
__device__ float g_cc[7446528];      // coupling coeffs [101,1152,64]
__device__ float g_v[103424];        // v [64,101,16]
__device__ float g_f1[262144];       // fc1 out [64,4096]
__device__ float g_f2[262144];       // fc2 out [64,4096]
__device__ u32   g_packA[10000000];  // packed hi|lo activations (per layer)
__device__ u32   g_packW[1400000];   // split weight planes: hi u16[]; lo u16[]

// ---------------------------------------------------------------------------
// bf16 hi/lo split: x ≈ hi + lo (both bf16 RNE). packed u32 = (hi<<16)|lo
// ---------------------------------------------------------------------------
__device__ __forceinline__ u32 pack_hilo(float x)
{
    u32 u  = __float_as_uint(x);
    u32 hi = (u + 0x7fffu + ((u >> 16) & 1u)) >> 16;
    float hf = __uint_as_float(hi << 16);
    u32 v  = __float_as_uint(x - hf);
    u32 lo = (v + 0x7fffu + ((v >> 16) & 1u)) >> 16;
    return (hi << 16) | lo;
}

__global__ void pack_act_k(const float* __restrict__ src, u32* __restrict__ dst, int n)
{
    int i = blockIdx.x * blockDim.x + threadIdx.x;
    if (i < n) dst[i] = pack_hilo(src[i]);
}

__global__ void pack_wsplit_k(const float* __restrict__ src,
                              u16* __restrict__ hi, u16* __restrict__ lo,
                              int M, int K, int Kpad, int tot)
{
    int i = blockIdx.x * blockDim.x + threadIdx.x;
    if (i >= tot) return;
    int m = i / Kpad, k = i - m * Kpad;
    float x = (m < M && k < K) ? src[(long)m * K + k] : 0.f;
    u32 p = pack_hilo(x);
    hi[i] = (u16)(p >> 16);
    lo[i] = (u16)(p & 0xffffu);
}

// ---------------------------------------------------------------------------
// mma.sync bf16 + cp.async helpers
// ---------------------------------------------------------------------------
__device__ __forceinline__ void mma_bf16(float* d, const u32* a, u32 b0, u32 b1)
{
    asm("mma.sync.aligned.m16n8k16.row.col.f32.bf16.bf16.f32 "
        "{%0,%1,%2,%3}, {%4,%5,%6,%7}, {%8,%9}, {%0,%1,%2,%3};"
        : "+f"(d[0]), "+f"(d[1]), "+f"(d[2]), "+f"(d[3])
        : "r"(a[0]), "r"(a[1]), "r"(a[2]), "r"(a[3]), "r"(b0), "r"(b1));
}

__device__ __forceinline__ void cp_async16(u32 dst, const void* src)
{
    asm volatile("cp.async.ca.shared.global [%0], [%1], 16;"
                 :: "r"(dst), "l"(src) : "memory");
}
__device__ __forceinline__ void cp_commit()
{
    asm volatile("cp.async.commit_group;" ::: "memory");
}
template<int N> __device__ __forceinline__ void cp_wait()
{
    asm volatile("cp.async.wait_group %0;" :: "n"(N) : "memory");
}

// ---------------------------------------------------------------------------
// Implicit-GEMM conv on mma.sync bf16, 2-term split (3 passes).
// 128x128 tile, BK=32, 8 warps (4x2), double-buffered smem, 80B row stride.
// NO min-blocks clamp (round-6 regression: reg cap forced spills).
// Epilogue: smem-staged transpose -> coalesced n-contiguous stores (round 9).
// ---------------------------------------------------------------------------
static constexpr int CV_ROWB  = 80;
static constexpr int CV_ARR   = 128 * CV_ROWB;           // 10240
static constexpr int CV_AH = 0, CV_AL = CV_ARR, CV_BH = 2 * CV_ARR, CV_BL = 3 * CV_ARR;
static constexpr int CV_STAGE = 4 * CV_ARR;              // 40960
static constexpr int CV_SMEM  = 2 * CV_STAGE;            // 81920

template<int KH, int KW, int SS, int PP>
__global__ __launch_bounds__(256)
void convhmma_k(const u16* __restrict__ whi, const u16* __restrict__ wlo,
                const u32* __restrict__ pin, const float* __restrict__ bias,
                float* __restrict__ outp,
                int M, int C, int H, int W, int OH, int OW,
                int K, int Kpad, int relu)
{
    extern __shared__ char smem[];
    const u32 sbase = (u32)__cvta_generic_to_shared(smem);

    const int tid  = threadIdx.x;
    const int wid  = tid >> 5, lane = tid & 31;
    const int g    = lane >> 2, qi = lane & 3;
    const int mwarp = (wid >> 1) * 32, nwarp = (wid & 1) * 64;
    const int KHW  = KH * KW;
    const int OHW  = OH * OW;
    const int N    = 64 * OHW;
    const int m0   = blockIdx.y * 128, n0 = blockIdx.x * 128;

    const int lrow = tid & 127;
    const int half = tid >> 7;

    const int gn = n0 + lrow;
    const bool nvalid = gn < N;
    const int bn = nvalid ? gn : 0;
    const int ow = bn % OW;
    const int t1 = bn / OW;
    const int oh = t1 % OH;
    const int bb = t1 / OH;
    const int ihb = oh * SS - PP, iwb = ow * SS - PP;
    const u32* inb = pin + (long)bb * C * H * W;

    const int nstage = Kpad / 32;

    auto issueA = [&](int ck, int buf) {
        const u16* srch = whi + (long)(m0 + lrow) * Kpad + ck * 32 + half * 16;
        const u16* srcl = wlo + (long)(m0 + lrow) * Kpad + ck * 32 + half * 16;
        u32 d = sbase + buf * CV_STAGE + lrow * CV_ROWB + half * 32;
        cp_async16(d + CV_AH,      srch);
        cp_async16(d + CV_AH + 16, srch + 8);
        cp_async16(d + CV_AL,      srcl);
        cp_async16(d + CV_AL + 16, srcl + 8);
        cp_commit();
    };

    u32 breg[16];
    auto loadB = [&](int ck) {
        int gk0 = ck * 32 + half * 16;
        int cc = gk0 / KHW;
        int r  = gk0 - cc * KHW;
        int kh = r / KW;
        int kw = r - kh * KW;
#pragma unroll
        for (int t = 0; t < 16; t++) {
            u32 v = 0u;
            if (nvalid && gk0 + t < K) {
                int ih = ihb + kh, iw = iwb + kw;
                if ((unsigned)ih < (unsigned)H && (unsigned)iw < (unsigned)W)
                    v = inb[((long)cc * H + ih) * W + iw];
            }
            breg[t] = v;
            if (++kw == KW) { kw = 0; if (++kh == KH) { kh = 0; ++cc; } }
        }
    };
    auto storeB = [&](int buf) {
        u32 h[8], l[8];
#pragma unroll
        for (int t = 0; t < 8; t++) {
            h[t] = __byte_perm(breg[2 * t], breg[2 * t + 1], 0x7632);
            l[t] = __byte_perm(breg[2 * t], breg[2 * t + 1], 0x5410);
        }
        char* d = smem + buf * CV_STAGE + lrow * CV_ROWB + half * 32;
        *(uint4*)(d + CV_BH)      = make_uint4(h[0], h[1], h[2], h[3]);
        *(uint4*)(d + CV_BH + 16) = make_uint4(h[4], h[5], h[6], h[7]);
        *(uint4*)(d + CV_BL)      = make_uint4(l[0], l[1], l[2], l[3]);
        *(uint4*)(d + CV_BL + 16) = make_uint4(l[4], l[5], l[6], l[7]);
    };

    float acc[2][8][4];
#pragma unroll
    for (int i = 0; i < 2; i++)
#pragma unroll
        for (int j = 0; j < 8; j++)
#pragma unroll
            for (int q = 0; q < 4; q++) acc[i][j][q] = 0.f;

    int buf = 0;
    issueA(0, 0);
    loadB(0);

    for (int ck = 0; ck < nstage; ck++) {
        storeB(buf);
        cp_wait<0>();
        __syncthreads();
        if (ck + 1 < nstage) {
            issueA(ck + 1, buf ^ 1);
            loadB(ck + 1);
        }

        const char* st = smem + buf * CV_STAGE;
#pragma unroll
        for (int kk = 0; kk < 2; kk++) {
            u32 ah[2][4], al[2][4];
#pragma unroll
            for (int mt = 0; mt < 2; mt++) {
                const char* rA = st + (mwarp + mt * 16 + g) * CV_ROWB + kk * 32 + qi * 4;
                ah[mt][0] = *(const u32*)(rA + CV_AH);
                ah[mt][1] = *(const u32*)(rA + CV_AH + 8 * CV_ROWB);
                ah[mt][2] = *(const u32*)(rA + CV_AH + 16);
                ah[mt][3] = *(const u32*)(rA + CV_AH + 8 * CV_ROWB + 16);
                al[mt][0] = *(const u32*)(rA + CV_AL);
                al[mt][1] = *(const u32*)(rA + CV_AL + 8 * CV_ROWB);
                al[mt][2] = *(const u32*)(rA + CV_AL + 16);
                al[mt][3] = *(const u32*)(rA + CV_AL + 8 * CV_ROWB + 16);
            }
#pragma unroll
            for (int nt = 0; nt < 8; nt++) {
                const char* rB = st + (nwarp + nt * 8 + g) * CV_ROWB + kk * 32 + qi * 4;
                u32 bh0 = *(const u32*)(rB + CV_BH);
                u32 bh1 = *(const u32*)(rB + CV_BH + 16);
                u32 bl0 = *(const u32*)(rB + CV_BL);
                u32 bl1 = *(const u32*)(rB + CV_BL + 16);
                mma_bf16(acc[0][nt], ah[0], bh0, bh1);
                mma_bf16(acc[1][nt], ah[1], bh0, bh1);
                mma_bf16(acc[0][nt], al[0], bh0, bh1);
                mma_bf16(acc[1][nt], al[1], bh0, bh1);
                mma_bf16(acc[0][nt], ah[0], bl0, bl1);
                mma_bf16(acc[1][nt], ah[1], bl0, bl1);
            }
        }
        __syncthreads();
        buf ^= 1;
    }

    // ---- epilogue v2: stage warp tile (32m x 64n) in smem, then write
    //      n-contiguous coalesced runs. smem free after final __syncthreads.
    {
        float* tw = (float*)smem + wid * 2176;   // 32 rows x 68 floats
#pragma unroll
        for (int mt = 0; mt < 2; mt++)
#pragma unroll
            for (int nt = 0; nt < 8; nt++)
#pragma unroll
                for (int q = 0; q < 2; q++) {
                    int ln = nt * 8 + 2 * qi + q;
                    tw[(mt * 16 + g) * 68 + ln]     = acc[mt][nt][q];
                    tw[(mt * 16 + 8 + g) * 68 + ln] = acc[mt][nt][2 + q];
                }
        __syncwarp();

        int nA = n0 + nwarp + lane;
        int nB = nA + 32;
        bool okA = nA < N, okB = nB < N;
        int ncA = okA ? nA : 0, ncB = okB ? nB : 0;
        int bA = ncA / OHW, pA = ncA - bA * OHW;
        int bB = ncB / OHW, pB = ncB - bB * OHW;
        long baseA = (long)bA * M * OHW + pA;
        long baseB = (long)bB * M * OHW + pB;

        for (int r = 0; r < 32; r++) {
            int m = m0 + mwarp + r;
            if (m >= M) break;
            float bv = bias[m];
            float vA = tw[r * 68 + lane] + bv;
            float vB = tw[r * 68 + 32 + lane] + bv;
            if (relu) { vA = fmaxf(vA, 0.f); vB = fmaxf(vB, 0.f); }
            long moff = (long)m * OHW;
            if (okA) outp[baseA + moff] = vA;
            if (okB) outp[baseB + moff] = vB;
        }
    }
}

// ---------------------------------------------------------------------------
// 64x64-tile f32x2 GEMM (FC layers).  B given [N,K]; C[n*M+m]
// ---------------------------------------------------------------------------
__global__ __launch_bounds__(256, 2) void gemm64_k(
    const float* __restrict__ A, const float* __restrict__ Bm,
    const float* __restrict__ bias, float* __restrict__ Cout,
    int M, int N, int K, int relu)
{
    __shared__ __align__(16) float As[16][64];
    __shared__ __align__(16) float Bs[16][64];

    const int tid = threadIdx.x;
    const int m0 = blockIdx.y * 64, n0 = blockIdx.x * 64;
    const int tx = tid & 15, ty = tid >> 4;
    const int lm = tid & 63;
    const int lk4 = (tid >> 6) * 4;

    ull acc[4][2];
#pragma unroll
    for (int i = 0; i < 4; i++) { acc[i][0] = 0ULL; acc[i][1] = 0ULL; }

    for (int k0 = 0; k0 < K; k0 += 16) {
        {
            int gm = m0 + lm;
            if (gm < M) {
                float4 av = *(const float4*)&A[(long)gm * K + k0 + lk4];
                As[lk4 + 0][lm] = av.x; As[lk4 + 1][lm] = av.y;
                As[lk4 + 2][lm] = av.z; As[lk4 + 3][lm] = av.w;
            } else {
                As[lk4 + 0][lm] = 0.f; As[lk4 + 1][lm] = 0.f;
                As[lk4 + 2][lm] = 0.f; As[lk4 + 3][lm] = 0.f;
            }
        }
        {
            int gn = n0 + lm;
            if (gn < N) {
                float4 bv = *(const float4*)&Bm[(long)gn * K + k0 + lk4];
                Bs[lk4 + 0][lm] = bv.x; Bs[lk4 + 1][lm] = bv.y;
                Bs[lk4 + 2][lm] = bv.z; Bs[lk4 + 3][lm] = bv.w;
            } else {
                Bs[lk4 + 0][lm] = 0.f; Bs[lk4 + 1][lm] = 0.f;
                Bs[lk4 + 2][lm] = 0.f; Bs[lk4 + 3][lm] = 0.f;
            }
        }
        __syncthreads();
#pragma unroll
        for (int kk = 0; kk < 16; kk++) {
            float4 a4 = *(const float4*)&As[kk][ty * 4];
            ulonglong2 bv = *(const ulonglong2*)&Bs[kk][tx * 4];
            ull bp[2] = {bv.x, bv.y};
            float av[4] = {a4.x, a4.y, a4.z, a4.w};
#pragma unroll
            for (int i = 0; i < 4; i++) {
                ull sa;
                asm("mov.b64 %0, {%1, %1};" : "=l"(sa) : "f"(av[i]));
#pragma unroll
                for (int j = 0; j < 2; j++)
                    asm("fma.rn.f32x2 %0, %1, %2, %0;"
                        : "+l"(acc[i][j]) : "l"(sa), "l"(bp[j]));
            }
        }
        __syncthreads();
    }

#pragma unroll
    for (int i = 0; i < 4; i++) {
        int m = m0 + ty * 4 + i;
        if (m >= M) continue;
        float bv = bias ? bias[m] : 0.f;
#pragma unroll
        for (int j = 0; j < 2; j++) {
            float lo, hi;
            asm("mov.b64 {%0, %1}, %2;" : "=f"(lo), "=f"(hi) : "l"(acc[i][j]));
            float v0 = lo + bv, v1 = hi + bv;
            if (relu) { if (v0 < 0.f) v0 = 0.f; if (v1 < 0.f) v1 = 0.f; }
            int nA = n0 + tx * 4 + 2 * j, nB = nA + 1;
            if (nA < N) Cout[(long)nA * M + m] = v0;
            if (nB < N) Cout[(long)nB * M + m] = v1;
        }
    }
}

// ---------------------------------------------------------------------------
// MaxPool (floor mode)
// ---------------------------------------------------------------------------
__global__ void maxpool_k(const float* __restrict__ in, float* __restrict__ out,
                          int C, int H, int W, int OH, int OW,
                          int ks, int stride, int pad, int total)
{
    int idx = blockIdx.x * blockDim.x + threadIdx.x;
    if (idx >= total) return;
    int ow = idx % OW;
    int t = idx / OW;
    int oh = t % OH; t /= OH;
    int c = t % C;
    int b = t / C;
    const float* p = in + (long)(b * C + c) * H * W;
    float mx = -3.4e38f;
    int h0 = oh * stride - pad, w0 = ow * stride - pad;
    for (int kh = 0; kh < ks; kh++) {
        int ih = h0 + kh;
        if (ih < 0 || ih >= H) continue;
        for (int kw = 0; kw < ks; kw++) {
            int iw = w0 + kw;
            if (iw < 0 || iw >= W) continue;
            float v = p[ih * W + iw];
            if (v > mx) mx = v;
        }
    }
    out[idx] = mx;
}

// ---------------------------------------------------------------------------
// squash8 (primary caps) -> u [64][1152][8]
// ---------------------------------------------------------------------------
__global__ void squash8_k(const float* __restrict__ p, float* __restrict__ u, int ncaps)
{
    int idx = blockIdx.x * blockDim.x + threadIdx.x;
    if (idx >= ncaps) return;
    const float4* ip = (const float4*)(p + (long)idx * 8);
    float4 a = ip[0], b = ip[1];
    float sq = a.x*a.x + a.y*a.y + a.z*a.z + a.w*a.w
             + b.x*b.x + b.y*b.y + b.z*b.z + b.w*b.w;
    float sc = (sq / (1.f + sq)) / sqrtf(sq + 1e-8f);
    float4* op = (float4*)(u + (long)idx * 8);
    op[0] = make_float4(a.x*sc, a.y*sc, a.z*sc, a.w*sc);
    op[1] = make_float4(b.x*sc, b.y*sc, b.z*sc, b.w*sc);
}

// ---------------------------------------------------------------------------
// u transpose: ut[i][b][8] = u[b][i][8]
// ---------------------------------------------------------------------------
__global__ void ut_k(const float* __restrict__ u, float* __restrict__ ut)
{
    int idx = blockIdx.x * blockDim.x + threadIdx.x;   // 73728
    if (idx >= 73728) return;
    int i = idx >> 6, b = idx & 63;
    const float4* src = (const float4*)(u + ((long)b * 1152 + i) * 8);
    float4 a0 = src[0], a1 = src[1];
    float4* dst = (float4*)(ut + (long)idx * 8);
    dst[0] = a0; dst[1] = a1;
}

// ---------------------------------------------------------------------------
// Fused routing — x_hat recomputed on the fly from W (L2-resident) + u.
// ---------------------------------------------------------------------------
static constexpr int FR_SMEM = 16384 * 4 + 4 * 64 * 17 * 4;   // 82944
static constexpr int FU_SMEM = 16384 * 4;                     // 65536

__global__ __launch_bounds__(256) void fr_k(
    const float* __restrict__ Wc, const float* __restrict__ ut,
    const float* __restrict__ cct, float* __restrict__ sp)
{
    extern __shared__ float sm[];
    float* Wsm = sm;                 // 16384 floats, rows d-major [il][d*16+o]
    float* red = sm + 16384;         // 4*64*17
    const int tid = threadIdx.x;
    const int p = blockIdx.x, j = blockIdx.y;
    const int i0 = p * 128;
    const int s = tid >> 6, b = tid & 63;

    const float* wsrc = Wc + ((long)j * 1152 + i0) * 128;
    for (int idx = tid; idx < 16384; idx += 256) {
        int row = idx >> 7, r = idx & 127;
        Wsm[row * 128 + (r & 7) * 16 + (r >> 3)] = wsrc[idx];
    }
    __syncthreads();

    ull accp[8];
#pragma unroll
    for (int op = 0; op < 8; op++) accp[op] = 0ULL;

    for (int k = 0; k < 32; k++) {
        const int il = s + 4 * k;
        const int i = i0 + il;
        const float4* up = (const float4*)(ut + ((long)i * 64 + b) * 8);
        float4 u0 = up[0], u1 = up[1];
        float ud[8] = {u0.x, u0.y, u0.z, u0.w, u1.x, u1.y, u1.z, u1.w};
        float cw = cct ? cct[((long)j * 1152 + i) * 64 + b] : (1.f / 101.f);
        const float* wr = Wsm + il * 128;
        ull xp[8];
#pragma unroll
        for (int op = 0; op < 8; op++) xp[op] = 0ULL;
#pragma unroll
        for (int d = 0; d < 8; d++) {
            ull us;
            asm("mov.b64 %0, {%1, %1};" : "=l"(us) : "f"(ud[d]));
            const ulonglong2* wp2 = (const ulonglong2*)(wr + d * 16);
#pragma unroll
            for (int q = 0; q < 4; q++) {
                ulonglong2 wv = wp2[q];
                asm("fma.rn.f32x2 %0, %1, %2, %0;" : "+l"(xp[2*q])   : "l"(us), "l"(wv.x));
                asm("fma.rn.f32x2 %0, %1, %2, %0;" : "+l"(xp[2*q+1]) : "l"(us), "l"(wv.y));
            }
        }
        ull cws;
        asm("mov.b64 %0, {%1, %1};" : "=l"(cws) : "f"(cw));
#pragma unroll
        for (int op = 0; op < 8; op++)
            asm("fma.rn.f32x2 %0, %1, %2, %0;" : "+l"(accp[op]) : "l"(cws), "l"(xp[op]));
    }

    float* rr = red + (s * 64 + b) * 17;
#pragma unroll
    for (int op = 0; op < 8; op++) {
        float lo, hi;
        asm("mov.b64 {%0, %1}, %2;" : "=f"(lo), "=f"(hi) : "l"(accp[op]));
        rr[2 * op] = lo; rr[2 * op + 1] = hi;
    }
    __syncthreads();
    for (int t = tid; t < 1024; t += 256) {
        int ob = t >> 4, oo = t & 15;
        float sum = red[(ob) * 17 + oo] + red[(64 + ob) * 17 + oo]
                  + red[(128 + ob) * 17 + oo] + red[(192 + ob) * 17 + oo];
        sp[(((long)p * 64 + ob) * 101 + j) * 16 + oo] = sum;
    }
}

// combine 9 partials + squash -> v [b][j][o]
__global__ void fs_k(const float* __restrict__ sp, float* __restrict__ vout, int total)
{
    int idx = blockIdx.x * blockDim.x + threadIdx.x;
    if (idx >= total) return;               // 103424
    float sum = 0.f;
#pragma unroll
    for (int p = 0; p < 9; p++) sum += sp[(long)p * 103424 + idx];
    float sq = sum * sum;
#pragma unroll
    for (int off = 8; off > 0; off >>= 1)
        sq += __shfl_xor_sync(0xffffffffu, sq, off, 16);
    float sc = (sq / (1.f + sq)) / sqrtf(sq + 1e-8f);
    vout[idx] = sum * sc;
}

// fu_k: bl[j][i][b] (+)= sum_o v[b,j,o] * (W[j,i]·u[b,i])_o
__global__ __launch_bounds__(256) void fu_k(
    const float* __restrict__ Wc, const float* __restrict__ ut,
    const float* __restrict__ v, float* __restrict__ bl, int overwrite)
{
    extern __shared__ float sm[];
    float* Wsm = sm;
    const int tid = threadIdx.x;
    const int p = blockIdx.x, j = blockIdx.y;
    const int i0 = p * 128;
    const int s = tid >> 6, b = tid & 63;

    const float* wsrc = Wc + ((long)j * 1152 + i0) * 128;
    for (int idx = tid; idx < 16384; idx += 256) {
        int row = idx >> 7, r = idx & 127;
        Wsm[row * 128 + (r & 7) * 16 + (r >> 3)] = wsrc[idx];
    }
    __syncthreads();

    ull vp[8];
    const ull* vptr = (const ull*)(v + ((long)b * 101 + j) * 16);
#pragma unroll
    for (int op = 0; op < 8; op++) vp[op] = vptr[op];

    for (int k = 0; k < 32; k++) {
        const int il = s + 4 * k;
        const int i = i0 + il;
        const float4* up = (const float4*)(ut + ((long)i * 64 + b) * 8);
        float4 u0 = up[0], u1 = up[1];
        float ud[8] = {u0.x, u0.y, u0.z, u0.w, u1.x, u1.y, u1.z, u1.w};
        const float* wr = Wsm + il * 128;
        ull xp[8];
#pragma unroll
        for (int op = 0; op < 8; op++) xp[op] = 0ULL;
#pragma unroll
        for (int d = 0; d < 8; d++) {
            ull us;
            asm("mov.b64 %0, {%1, %1};" : "=l"(us) : "f"(ud[d]));
            const ulonglong2* wp2 = (const ulonglong2*)(wr + d * 16);
#pragma unroll
            for (int q = 0; q < 4; q++) {
                ulonglong2 wv = wp2[q];
                asm("fma.rn.f32x2 %0, %1, %2, %0;" : "+l"(xp[2*q])   : "l"(us), "l"(wv.x));
                asm("fma.rn.f32x2 %0, %1, %2, %0;" : "+l"(xp[2*q+1]) : "l"(us), "l"(wv.y));
            }
        }
        ull dp = 0ULL;
#pragma unroll
        for (int op = 0; op < 8; op++)
            asm("fma.rn.f32x2 %0, %1, %2, %0;" : "+l"(dp) : "l"(vp[op]), "l"(xp[op]));
        float lo, hi;
        asm("mov.b64 {%0, %1}, %2;" : "=f"(lo), "=f"(hi) : "l"(dp));
        float d = lo + hi;
        long addr = ((long)j * 1152 + i) * 64 + b;
        bl[addr] = overwrite ? d : bl[addr] + d;
    }
}

// softmax over j for each (i,b); bl/cct layout [101][1152][64]
__global__ void softmax_t_k(const float* __restrict__ bl, float* __restrict__ cct, int total)
{
    int idx = blockIdx.x * blockDim.x + threadIdx.x;
    if (idx >= total) return;    // 73728 = 1152*64
    const float* p = bl + idx;
    float mx = p[0];
    for (int j = 1; j < 101; j++) {
        float t = p[(long)j * 73728];
        if (t > mx) mx = t;
    }
    float sum = 0.f;
    for (int j = 0; j < 101; j++) sum += expf(p[(long)j * 73728] - mx);
    float inv = 1.f / sum;
    float* q = cct + idx;
    for (int j = 0; j < 101; j++) q[(long)j * 73728] = expf(p[(long)j * 73728] - mx) * inv;
}

// ---------------------------------------------------------------------------
// Host-side orchestration
// ---------------------------------------------------------------------------
static float* symaddr(const void* sym)
{
    void* p = nullptr;
    cudaGetSymbolAddress(&p, sym);
    return (float*)p;
}

template<int KH, int KW, int SS, int PP>
static void run_convhmma(const float* w, const float* in, const float* bias, float* outp,
                         int M, int C, int H, int Win, int OH, int OW, int relu,
                         u32* packW, u32* packA)
{
    const int K = C * KH * KW;
    const int Kpad = ((K + 31) / 32) * 32;
    const int Mpad = ((M + 127) / 128) * 128;
    u16* whi = (u16*)packW;
    u16* wlo = whi + (size_t)Mpad * Kpad;
    {
        int tot = Mpad * Kpad;
        pack_wsplit_k<<<(tot + 255) / 256, 256>>>(w, whi, wlo, M, K, Kpad, tot);
    }
    {
        int tot = 64 * C * H * Win;
        pack_act_k<<<(tot + 255) / 256, 256>>>(in, packA, tot);
    }
    static bool attr11 = false, attr5 = false, attr3 = false;
    bool& flag = (KH == 11) ? attr11 : (KH == 5) ? attr5 : attr3;
    if (!flag) {
        cudaFuncSetAttribute(convhmma_k<KH, KW, SS, PP>,
                             cudaFuncAttributeMaxDynamicSharedMemorySize, CV_SMEM);
        flag = true;
    }
    int N = 64 * OH * OW;
    dim3 grid((N + 127) / 128, Mpad / 128);
    convhmma_k<KH, KW, SS, PP><<<grid, 256, CV_SMEM>>>(whi, wlo, packA, bias, outp,
                                                       M, C, H, Win, OH, OW, K, Kpad, relu);
}

static void run_gemm64(const float* A, const float* Bm, const float* bias, float* C,
                       int M, int N, int K, int relu)
{
    dim3 grid((N + 63) / 64, (M + 63) / 64);
    gemm64_k<<<grid, 256>>>(A, Bm, bias, C, M, N, K, relu);
}

static void run_maxpool(const float* in, float* out, int C, int H, int W,
                        int OH, int OW, int ks, int stride, int pad)
{
    int total = 64 * C * OH * OW;
    maxpool_k<<<(total + 255) / 256, 256>>>(in, out, C, H, W, OH, OW, ks, stride, pad, total);
}

extern "C" void kernel_launch(void* const* d_in, const int* in_sizes, int n_in,
                              void* d_out, int out_size)
{
    const float* x      = (const float*)d_in[0];
    const float* w1     = (const float*)d_in[1];
    const float* b1     = (const float*)d_in[2];
    const float* w2     = (const float*)d_in[3];
    const float* b2     = (const float*)d_in[4];
    const float* w3     = (const float*)d_in[5];
    const float* b3     = (const float*)d_in[6];
    const float* w4     = (const float*)d_in[7];
    const float* b4     = (const float*)d_in[8];
    const float* w5     = (const float*)d_in[9];
    const float* b5     = (const float*)d_in[10];
    const float* pc_w   = (const float*)d_in[11];
    const float* pc_b   = (const float*)d_in[12];
    const float* caps_W = (const float*)d_in[13];
    const float* fc1_w  = (const float*)d_in[14];
    const float* fc1_b  = (const float*)d_in[15];
    const float* fc2_w  = (const float*)d_in[16];
    const float* fc2_b  = (const float*)d_in[17];
    const float* fc3_w  = (const float*)d_in[18];
    const float* fc3_b  = (const float*)d_in[19];
    float* out = (float*)d_out;

    float* a1  = symaddr(g_a1);
    float* p1  = symaddr(g_p1);
    float* a2  = symaddr(g_a2);
    float* p2  = symaddr(g_p2);
    float* a3  = symaddr(g_a3);
    float* a4  = symaddr(g_a4);
    float* a5  = symaddr(g_a5);
    float* p3  = symaddr(g_p3);
    float* pc  = symaddr(g_pc);
    float* u   = symaddr(g_u);
    float* ut  = symaddr(g_ut);
    float* sp  = symaddr(g_sp);
    float* bl  = symaddr(g_bl);
    float* cc  = symaddr(g_cc);
    float* v   = symaddr(g_v);
    float* f1  = symaddr(g_f1);
    float* f2  = symaddr(g_f2);
    u32* packA = (u32*)symaddr(g_packA);
    u32* packW = (u32*)symaddr(g_packW);

    // ---- conv stack ----
    run_convhmma<11, 11, 4, 0>(w1, x, b1, a1, 96, 3, 227, 227, 55, 55, 1, packW, packA);
    run_maxpool(a1, p1, 96, 55, 55, 27, 27, 3, 2, 0);

    run_convhmma<5, 5, 1, 2>(w2, p1, b2, a2, 256, 96, 27, 27, 27, 27, 1, packW, packA);
    run_maxpool(a2, p2, 256, 27, 27, 14, 14, 3, 2, 1);

    run_convhmma<3, 3, 1, 1>(w3, p2, b3, a3, 384, 256, 14, 14, 14, 14, 1, packW, packA);
    run_convhmma<3, 3, 1, 1>(w4, a3, b4, a4, 384, 384, 14, 14, 14, 14, 1, packW, packA);
    run_convhmma<3, 3, 1, 1>(w5, a4, b5, a5, 256, 384, 14, 14, 14, 14, 1, packW, packA);
    run_maxpool(a5, p3, 256, 14, 14, 6, 6, 3, 2, 0);

    run_convhmma<3, 3, 1, 1>(pc_w, p3, pc_b, pc, 256, 256, 6, 6, 6, 6, 0, packW, packA);

    // squash -> u [64,1152,8]; transpose -> ut [1152,64,8]
    squash8_k<<<(64 * 1152 + 255) / 256, 256>>>(pc, u, 64 * 1152);
    ut_k<<<288, 256>>>(u, ut);

    // ---- fused dynamic routing (x_hat never materialized) ----
    {
        static bool attrr = false;
        if (!attrr) {
            cudaFuncSetAttribute(fr_k, cudaFuncAttributeMaxDynamicSharedMemorySize, FR_SMEM);
            cudaFuncSetAttribute(fu_k, cudaFuncAttributeMaxDynamicSharedMemorySize, FU_SMEM);
            attrr = true;
        }
        dim3 rg(9, 101);
        fr_k<<<rg, 256, FR_SMEM>>>(caps_W, ut, nullptr, sp);
        fs_k<<<404, 256>>>(sp, v, 103424);
        fu_k<<<rg, 256, FU_SMEM>>>(caps_W, ut, v, bl, 1);
        softmax_t_k<<<288, 256>>>(bl, cc, 73728);
        fr_k<<<rg, 256, FR_SMEM>>>(caps_W, ut, cc, sp);
        fs_k<<<404, 256>>>(sp, v, 103424);
        fu_k<<<rg, 256, FU_SMEM>>>(caps_W, ut, v, bl, 0);
        softmax_t_k<<<288, 256>>>(bl, cc, 73728);
        fr_k<<<rg, 256, FR_SMEM>>>(caps_W, ut, cc, sp);
        fs_k<<<404, 256>>>(sp, v, 103424);
    }

    // ---- MLP head ----
    run_gemm64(fc1_w, v, fc1_b, f1, 4096, 64, 1616, 1);
    run_gemm64(fc2_w, f1, fc2_b, f2, 4096, 64, 4096, 1);
    run_gemm64(fc3_w, f2, fc3_b, out, 101, 64, 4096, 0);
}